// round 3
// baseline (speedup 1.0000x reference)
#include <cuda_runtime.h>
#include <math.h>

// Problem constants (fixed shapes per reference)
#define NN 100000
#define FF 128
#define CC 40
#define EE 1600000
#define SCAN_BLOCKS ((NN + 1 + 1023) / 1024)   // 98

// Scratch (device globals — no allocation allowed in kernel_launch)
__device__ float g_bufA[(size_t)NN * FF];
__device__ float g_bufB[(size_t)NN * FF];
__device__ float g_bufC[(size_t)NN * FF];
__device__ int   g_off[NN + 1];
__device__ int   g_cursor[NN];
__device__ int   g_ssrc[EE];
__device__ int   g_idx_is64;
__device__ int   g_bsum[128];

// ---------------------------------------------------------------------------
// Dtype sniffer (parallel): edge_index may arrive as int64 or int32.
// 32 lanes each sample one int64 slot within [0, E); any out-of-range value
// means the buffer is really int32 (two packed indices per 8 bytes).
// ---------------------------------------------------------------------------
__global__ void k_detect(const long long* __restrict__ ei, int e, int n) {
    int lane = threadIdx.x;
    long long step = e / 32; if (step < 1) step = 1;
    long long i = lane * step;
    int bad = 0;
    if (i < e) {
        long long v = ei[i];
        bad = (v < 0 || v >= n) ? 1 : 0;
    }
    unsigned m = __ballot_sync(0xffffffffu, bad);
    if (lane == 0) g_idx_is64 = (m == 0u) ? 1 : 0;
}

__device__ __forceinline__ int load_idx(const void* ei, long long elem, int is64) {
    return is64 ? (int)((const long long*)ei)[elem] : ((const int*)ei)[elem];
}

// ---------------------------------------------------------------------------
// CSR construction: zero -> histogram -> hierarchical scan -> scatter
// ---------------------------------------------------------------------------
__global__ void k_zero_off(int n) {
    int i = blockIdx.x * blockDim.x + threadIdx.x;
    if (i <= n) g_off[i] = 0;
}

__global__ void k_hist(const void* __restrict__ ei, int e, int n) {
    int i = blockIdx.x * blockDim.x + threadIdx.x;
    if (i >= e) return;
    int is64 = g_idx_is64;
    int d = load_idx(ei, (long long)e + i, is64);   // dst row lives at offset E
    if ((unsigned)d < (unsigned)n) atomicAdd(&g_off[d + 1], 1);
}

// Pass 1: per-block (1024 elems) inclusive scan; block totals to g_bsum.
__global__ void k_scan1(int n) {
    __shared__ int wsum[32];
    int tid = threadIdx.x, lane = tid & 31, wid = tid >> 5;
    int gid = blockIdx.x * 1024 + tid;
    int v = (gid <= n) ? g_off[gid] : 0;
    #pragma unroll
    for (int d = 1; d < 32; d <<= 1) {
        int t = __shfl_up_sync(0xffffffffu, v, d);
        if (lane >= d) v += t;
    }
    if (lane == 31) wsum[wid] = v;
    __syncthreads();
    if (wid == 0) {
        int w = wsum[lane];
        #pragma unroll
        for (int d = 1; d < 32; d <<= 1) {
            int t = __shfl_up_sync(0xffffffffu, w, d);
            if (lane >= d) w += t;
        }
        wsum[lane] = w;
    }
    __syncthreads();
    if (wid > 0) v += wsum[wid - 1];
    if (gid <= n) g_off[gid] = v;
    if (tid == 1023) g_bsum[blockIdx.x] = v;   // block total (tail padded with 0)
}

// Pass 2: exclusive scan of <=128 block totals (single block, 128 threads).
__global__ void k_scan2(int nblocks) {
    __shared__ int sh[128];
    int tid = threadIdx.x;
    int v = (tid < nblocks) ? g_bsum[tid] : 0;
    sh[tid] = v;
    __syncthreads();
    // simple Hillis-Steele inclusive in shared
    for (int d = 1; d < 128; d <<= 1) {
        int t = (tid >= d) ? sh[tid - d] : 0;
        __syncthreads();
        sh[tid] += t;
        __syncthreads();
    }
    int excl = (tid == 0) ? 0 : sh[tid - 1];
    if (tid < nblocks) g_bsum[tid] = excl;
}

// Pass 3: add block offsets; also init cursor.
__global__ void k_scan3(int n) {
    int gid = blockIdx.x * 1024 + threadIdx.x;
    if (gid > n) return;
    int v = g_off[gid] + g_bsum[blockIdx.x];
    g_off[gid] = v;
    if (gid < n) g_cursor[gid] = v;
}

__global__ void k_scatter(const void* __restrict__ ei, int e, int n) {
    int i = blockIdx.x * blockDim.x + threadIdx.x;
    if (i >= e) return;
    int is64 = g_idx_is64;
    int s = load_idx(ei, (long long)i, is64);
    int d = load_idx(ei, (long long)e + i, is64);
    if ((unsigned)d < (unsigned)n && (unsigned)s < (unsigned)n) {
        int pos = atomicAdd(&g_cursor[d], 1);
        if (pos < EE) g_ssrc[pos] = s;
    }
}

// ---------------------------------------------------------------------------
// GIN aggregation: out[i] = (1+eps)*h[i] + sum_{j->i} h[j]
// One warp per node, float4 per lane (128 floats = 32 float4).
// ---------------------------------------------------------------------------
__global__ void k_agg(const float* __restrict__ hin, float* __restrict__ hout,
                      const float* __restrict__ epsp, int n) {
    int g = blockIdx.x * blockDim.x + threadIdx.x;
    int node = g >> 5;
    if (node >= n) return;
    int lane = g & 31;
    float sc = 1.0f + *epsp;
    const float4* base = (const float4*)hin;
    float4 acc = __ldg(&base[(size_t)node * 32 + lane]);
    acc.x *= sc; acc.y *= sc; acc.z *= sc; acc.w *= sc;
    int beg = g_off[node], end = g_off[node + 1];
    #pragma unroll 4
    for (int e = beg; e < end; e++) {
        int s = g_ssrc[e];
        float4 v = __ldg(&base[(size_t)s * 32 + lane]);
        acc.x += v.x; acc.y += v.y; acc.z += v.z; acc.w += v.w;
    }
    *(float4*)&hout[(size_t)node * FF + lane * 4] = acc;
}

// ---------------------------------------------------------------------------
// GEMM: out[n,c] = relu(in @ w + b), K=128, OUT=128, packed f32x2 FMAs.
// Block: 256 threads = 16 row-groups x 16 col-groups.
// Tile: 64 rows x 128 cols. Thread computes 4 rows x 8 cols (4 f32x2 pairs).
// Weights (64KB) + x-tile (32KB) in smem.
// ---------------------------------------------------------------------------
__device__ __forceinline__ unsigned long long pack2(float x) {
    unsigned long long r;
    asm("mov.b64 %0, {%1, %1};" : "=l"(r) : "r"(__float_as_uint(x)));
    return r;
}
__device__ __forceinline__ void ffma2(unsigned long long& d,
                                      unsigned long long a, unsigned long long b) {
    asm("fma.rn.f32x2 %0, %1, %2, %0;" : "+l"(d) : "l"(a), "l"(b));
}

__global__ void k_gemm_relu(const float* __restrict__ in, const float* __restrict__ w,
                            const float* __restrict__ bias, float* __restrict__ out,
                            int nrows) {
    extern __shared__ float sm[];
    float* ws = sm;           // 128*128 = 16384 floats (64KB)
    float* xs = sm + 16384;   // 64*128  =  8192 floats (32KB)
    int tid = threadIdx.x;
    for (int i = tid; i < 16384; i += 256) ws[i] = w[i];
    int cg = tid & 15;           // col group (8 cols)
    int rg = tid >> 4;           // row group (4 rows)
    int col0 = cg * 8;
    int rbase = rg * 4;
    ulonglong2 b01 = *(const ulonglong2*)&bias[col0];
    ulonglong2 b23 = *(const ulonglong2*)&bias[col0 + 4];
    int ntiles = (nrows + 63) / 64;
    for (int tile = blockIdx.x; tile < ntiles; tile += gridDim.x) {
        int row0 = tile * 64;
        __syncthreads();
        for (int i = tid; i < 8192; i += 256) {
            int r = i >> 7, c = i & 127;
            int gr = row0 + r;
            xs[i] = (gr < nrows) ? in[(size_t)gr * FF + c] : 0.0f;
        }
        __syncthreads();
        unsigned long long acc[4][4];
        #pragma unroll
        for (int r = 0; r < 4; r++) {
            acc[r][0] = b01.x; acc[r][1] = b01.y;
            acc[r][2] = b23.x; acc[r][3] = b23.y;
        }
        #pragma unroll 4
        for (int k = 0; k < 128; k++) {
            ulonglong2 w01 = *(const ulonglong2*)&ws[k * 128 + col0];
            ulonglong2 w23 = *(const ulonglong2*)&ws[k * 128 + col0 + 4];
            #pragma unroll
            for (int r = 0; r < 4; r++) {
                unsigned long long xx = pack2(xs[(rbase + r) * 128 + k]);
                ffma2(acc[r][0], xx, w01.x);
                ffma2(acc[r][1], xx, w01.y);
                ffma2(acc[r][2], xx, w23.x);
                ffma2(acc[r][3], xx, w23.y);
            }
        }
        #pragma unroll
        for (int r = 0; r < 4; r++) {
            int gr = row0 + rbase + r;
            if (gr < nrows) {
                float4 o0, o1;
                o0.x = fmaxf(__uint_as_float((unsigned)(acc[r][0])), 0.0f);
                o0.y = fmaxf(__uint_as_float((unsigned)(acc[r][0] >> 32)), 0.0f);
                o0.z = fmaxf(__uint_as_float((unsigned)(acc[r][1])), 0.0f);
                o0.w = fmaxf(__uint_as_float((unsigned)(acc[r][1] >> 32)), 0.0f);
                o1.x = fmaxf(__uint_as_float((unsigned)(acc[r][2])), 0.0f);
                o1.y = fmaxf(__uint_as_float((unsigned)(acc[r][2] >> 32)), 0.0f);
                o1.z = fmaxf(__uint_as_float((unsigned)(acc[r][3])), 0.0f);
                o1.w = fmaxf(__uint_as_float((unsigned)(acc[r][3] >> 32)), 0.0f);
                *(float4*)&out[(size_t)gr * FF + col0] = o0;
                *(float4*)&out[(size_t)gr * FF + col0 + 4] = o1;
            }
        }
    }
}

// ---------------------------------------------------------------------------
// Final layer: out = log_softmax(in @ w4 + b4), K=128, C=40.
// One warp per row; lane owns col=lane and (lane<8) col=32+lane.
// ---------------------------------------------------------------------------
__global__ void k_final(const float* __restrict__ in, const float* __restrict__ w,
                        const float* __restrict__ bias, float* __restrict__ out,
                        int nrows) {
    __shared__ float ws[128 * 40];
    __shared__ float bs[40];
    __shared__ float xrow[8][128];
    int tid = threadIdx.x;
    for (int i = tid; i < 128 * 40; i += 256) ws[i] = w[i];
    if (tid < 40) bs[tid] = bias[tid];
    __syncthreads();
    int wid = tid >> 5, lane = tid & 31;
    for (int row = blockIdx.x * 8 + wid; row < nrows; row += gridDim.x * 8) {
        float4 xv = *(const float4*)&in[(size_t)row * FF + lane * 4];
        *(float4*)&xrow[wid][lane * 4] = xv;
        __syncwarp();
        float a0 = bs[lane];
        float a1 = (lane < 8) ? bs[32 + lane] : 0.0f;
        #pragma unroll 8
        for (int k = 0; k < 128; k++) {
            float xk = xrow[wid][k];
            a0 = fmaf(xk, ws[k * 40 + lane], a0);
            if (lane < 8) a1 = fmaf(xk, ws[k * 40 + 32 + lane], a1);
        }
        float m = a0;
        if (lane < 8) m = fmaxf(m, a1);
        #pragma unroll
        for (int d = 16; d; d >>= 1) m = fmaxf(m, __shfl_xor_sync(0xffffffffu, m, d));
        float s = expf(a0 - m) + ((lane < 8) ? expf(a1 - m) : 0.0f);
        #pragma unroll
        for (int d = 16; d; d >>= 1) s += __shfl_xor_sync(0xffffffffu, s, d);
        float lse = m + logf(s);
        out[(size_t)row * CC + lane] = a0 - lse;
        if (lane < 8) out[(size_t)row * CC + 32 + lane] = a1 - lse;
        __syncwarp();
    }
}

// ---------------------------------------------------------------------------
// Launcher
// ---------------------------------------------------------------------------
extern "C" void kernel_launch(void* const* d_in, const int* in_sizes, int n_in,
                              void* d_out, int out_size) {
    const float* x    = (const float*)d_in[0];
    const void*  ei   = d_in[1];
    const float* eps1 = (const float*)d_in[2];
    const float* w1   = (const float*)d_in[3];
    const float* b1   = (const float*)d_in[4];
    const float* w2   = (const float*)d_in[5];
    const float* b2   = (const float*)d_in[6];
    const float* eps2 = (const float*)d_in[7];
    const float* w3   = (const float*)d_in[8];
    const float* b3   = (const float*)d_in[9];
    const float* w4   = (const float*)d_in[10];
    const float* b4   = (const float*)d_in[11];
    float*       out  = (float*)d_out;

    int N = in_sizes[0] / FF;
    int E = in_sizes[1] / 2;
    if (N > NN) N = NN;
    if (E > EE) E = EE;

    const int smem_gemm = (16384 + 8192) * (int)sizeof(float);  // 96KB
    cudaFuncSetAttribute(k_gemm_relu, cudaFuncAttributeMaxDynamicSharedMemorySize,
                         smem_gemm);

    void *pA = nullptr, *pB = nullptr, *pC = nullptr;
    cudaGetSymbolAddress(&pA, g_bufA);
    cudaGetSymbolAddress(&pB, g_bufB);
    cudaGetSymbolAddress(&pC, g_bufC);
    float* bufA = (float*)pA;
    float* bufB = (float*)pB;
    float* bufC = (float*)pC;

    const int gemm_grid = 296;  // 2 blocks/SM * 148 SMs
    int scan_blocks = (N + 1 + 1023) / 1024;

    // Dtype sniff + CSR build (once per launch, reused by both aggregations)
    k_detect<<<1, 32>>>((const long long*)ei, E, N);
    k_zero_off<<<(N + 1 + 255) / 256, 256>>>(N);
    k_hist<<<(E + 255) / 256, 256>>>(ei, E, N);
    k_scan1<<<scan_blocks, 1024>>>(N);
    k_scan2<<<1, 128>>>(scan_blocks);
    k_scan3<<<scan_blocks, 1024>>>(N);
    k_scatter<<<(E + 255) / 256, 256>>>(ei, E, N);

    // Layer 1: agg -> Lin+ReLU -> Lin+ReLU
    {
        long long tw = (long long)N * 32;
        k_agg<<<(int)((tw + 255) / 256), 256>>>(x, bufA, eps1, N);
    }
    k_gemm_relu<<<gemm_grid, 256, smem_gemm>>>(bufA, w1, b1, bufB, N);
    k_gemm_relu<<<gemm_grid, 256, smem_gemm>>>(bufB, w2, b2, bufC, N);

    // Layer 2: agg -> Lin+ReLU -> Lin -> log_softmax
    {
        long long tw = (long long)N * 32;
        k_agg<<<(int)((tw + 255) / 256), 256>>>(bufC, bufA, eps2, N);
    }
    k_gemm_relu<<<gemm_grid, 256, smem_gemm>>>(bufA, w3, b3, bufB, N);
    k_final<<<(N + 7) / 8, 256>>>(bufB, w4, b4, out, N);
}

// round 4
// speedup vs baseline: 1.1606x; 1.1606x over previous
#include <cuda_runtime.h>
#include <math.h>

// Problem constants (fixed shapes per reference)
#define NN 100000
#define FF 128
#define CC 40
#define EE 1600000

// Scratch (device globals — no allocation allowed in kernel_launch)
__device__ float g_bufA[(size_t)NN * FF];
__device__ float g_bufB[(size_t)NN * FF];
__device__ float g_bufC[(size_t)NN * FF];
__device__ int   g_off[NN + 1];
__device__ int   g_cursor[NN];
__device__ int   g_ssrc[EE];
__device__ int   g_idx_is64;
__device__ int   g_bsum[128];

// ---------------------------------------------------------------------------
// Dtype sniffer (parallel): edge_index may arrive as int64 or int32.
// ---------------------------------------------------------------------------
__global__ void k_detect(const long long* __restrict__ ei, int e, int n) {
    int lane = threadIdx.x;
    long long step = e / 32; if (step < 1) step = 1;
    long long i = lane * step;
    int bad = 0;
    if (i < e) {
        long long v = ei[i];
        bad = (v < 0 || v >= n) ? 1 : 0;
    }
    unsigned m = __ballot_sync(0xffffffffu, bad);
    if (lane == 0) g_idx_is64 = (m == 0u) ? 1 : 0;
}

__device__ __forceinline__ int load_idx(const void* ei, long long elem, int is64) {
    return is64 ? (int)((const long long*)ei)[elem] : ((const int*)ei)[elem];
}

// ---------------------------------------------------------------------------
// CSR construction: zero -> histogram -> hierarchical scan -> scatter
// ---------------------------------------------------------------------------
__global__ void k_zero_off(int n) {
    int i = blockIdx.x * blockDim.x + threadIdx.x;
    if (i <= n) g_off[i] = 0;
}

__global__ void k_hist(const void* __restrict__ ei, int e, int n) {
    int i = blockIdx.x * blockDim.x + threadIdx.x;
    if (i >= e) return;
    int is64 = g_idx_is64;
    int d = load_idx(ei, (long long)e + i, is64);   // dst row lives at offset E
    if ((unsigned)d < (unsigned)n) atomicAdd(&g_off[d + 1], 1);
}

// Pass 1: per-block (1024 elems) inclusive scan; block totals to g_bsum.
__global__ void k_scan1(int n) {
    __shared__ int wsum[32];
    int tid = threadIdx.x, lane = tid & 31, wid = tid >> 5;
    int gid = blockIdx.x * 1024 + tid;
    int v = (gid <= n) ? g_off[gid] : 0;
    #pragma unroll
    for (int d = 1; d < 32; d <<= 1) {
        int t = __shfl_up_sync(0xffffffffu, v, d);
        if (lane >= d) v += t;
    }
    if (lane == 31) wsum[wid] = v;
    __syncthreads();
    if (wid == 0) {
        int w = wsum[lane];
        #pragma unroll
        for (int d = 1; d < 32; d <<= 1) {
            int t = __shfl_up_sync(0xffffffffu, w, d);
            if (lane >= d) w += t;
        }
        wsum[lane] = w;
    }
    __syncthreads();
    if (wid > 0) v += wsum[wid - 1];
    if (gid <= n) g_off[gid] = v;
    if (tid == 1023) g_bsum[blockIdx.x] = v;   // block total (tail padded with 0)
}

// Pass 2: exclusive scan of <=128 block totals (single block, 128 threads).
__global__ void k_scan2(int nblocks) {
    __shared__ int sh[128];
    int tid = threadIdx.x;
    int v = (tid < nblocks) ? g_bsum[tid] : 0;
    sh[tid] = v;
    __syncthreads();
    for (int d = 1; d < 128; d <<= 1) {
        int t = (tid >= d) ? sh[tid - d] : 0;
        __syncthreads();
        sh[tid] += t;
        __syncthreads();
    }
    int excl = (tid == 0) ? 0 : sh[tid - 1];
    if (tid < nblocks) g_bsum[tid] = excl;
}

// Pass 3: add block offsets; also init cursor.
__global__ void k_scan3(int n) {
    int gid = blockIdx.x * 1024 + threadIdx.x;
    if (gid > n) return;
    int v = g_off[gid] + g_bsum[blockIdx.x];
    g_off[gid] = v;
    if (gid < n) g_cursor[gid] = v;
}

__global__ void k_scatter(const void* __restrict__ ei, int e, int n) {
    int i = blockIdx.x * blockDim.x + threadIdx.x;
    if (i >= e) return;
    int is64 = g_idx_is64;
    int s = load_idx(ei, (long long)i, is64);
    int d = load_idx(ei, (long long)e + i, is64);
    if ((unsigned)d < (unsigned)n && (unsigned)s < (unsigned)n) {
        int pos = atomicAdd(&g_cursor[d], 1);
        if (pos < EE) g_ssrc[pos] = s;
    }
}

// ---------------------------------------------------------------------------
// GIN aggregation: out[i] = (1+eps)*h[i] + sum_{j->i} h[j]
// One warp per node, float4 per lane (128 floats = 32 float4).
// ---------------------------------------------------------------------------
__global__ void k_agg(const float* __restrict__ hin, float* __restrict__ hout,
                      const float* __restrict__ epsp, int n) {
    int g = blockIdx.x * blockDim.x + threadIdx.x;
    int node = g >> 5;
    if (node >= n) return;
    int lane = g & 31;
    float sc = 1.0f + *epsp;
    const float4* base = (const float4*)hin;
    float4 acc = __ldg(&base[(size_t)node * 32 + lane]);
    acc.x *= sc; acc.y *= sc; acc.z *= sc; acc.w *= sc;
    int beg = g_off[node], end = g_off[node + 1];
    #pragma unroll 4
    for (int e = beg; e < end; e++) {
        int s = g_ssrc[e];
        float4 v = __ldg(&base[(size_t)s * 32 + lane]);
        acc.x += v.x; acc.y += v.y; acc.z += v.z; acc.w += v.w;
    }
    *(float4*)&hout[(size_t)node * FF + lane * 4] = acc;
}

// ---------------------------------------------------------------------------
// GEMM: out[n,c] = relu(sum_k in[n,k] * w[k,c] + b[c]),  K=128, OUT=128
// Block: 256 threads, 32-row tiles, weights (64KB) + x-tile (16KB) in smem.
// Thread computes a 4x4 register tile. (Proven round-2 version.)
// ---------------------------------------------------------------------------
__global__ void k_gemm_relu(const float* __restrict__ in, const float* __restrict__ w,
                            const float* __restrict__ bias, float* __restrict__ out,
                            int nrows) {
    extern __shared__ float sm[];
    float* ws = sm;           // 128*128
    float* xs = sm + 16384;   // 32*128
    int tid = threadIdx.x;
    for (int i = tid; i < 16384; i += 256) ws[i] = w[i];
    int col4 = (tid & 31) * 4;
    int row4 = (tid >> 5) * 4;
    float4 bv = *(const float4*)&bias[col4];
    int ntiles = (nrows + 31) / 32;
    for (int tile = blockIdx.x; tile < ntiles; tile += gridDim.x) {
        int row0 = tile * 32;
        __syncthreads();
        for (int i = tid; i < 4096; i += 256) {
            int r = i >> 7, c = i & 127;
            int gr = row0 + r;
            xs[i] = (gr < nrows) ? in[(size_t)gr * FF + c] : 0.0f;
        }
        __syncthreads();
        float acc[4][4];
        #pragma unroll
        for (int r = 0; r < 4; r++) {
            acc[r][0] = bv.x; acc[r][1] = bv.y; acc[r][2] = bv.z; acc[r][3] = bv.w;
        }
        #pragma unroll 8
        for (int k = 0; k < 128; k++) {
            float4 wv = *(const float4*)&ws[k * 128 + col4];
            float x0 = xs[(row4 + 0) * 128 + k];
            float x1 = xs[(row4 + 1) * 128 + k];
            float x2 = xs[(row4 + 2) * 128 + k];
            float x3 = xs[(row4 + 3) * 128 + k];
            acc[0][0] = fmaf(x0, wv.x, acc[0][0]);
            acc[0][1] = fmaf(x0, wv.y, acc[0][1]);
            acc[0][2] = fmaf(x0, wv.z, acc[0][2]);
            acc[0][3] = fmaf(x0, wv.w, acc[0][3]);
            acc[1][0] = fmaf(x1, wv.x, acc[1][0]);
            acc[1][1] = fmaf(x1, wv.y, acc[1][1]);
            acc[1][2] = fmaf(x1, wv.z, acc[1][2]);
            acc[1][3] = fmaf(x1, wv.w, acc[1][3]);
            acc[2][0] = fmaf(x2, wv.x, acc[2][0]);
            acc[2][1] = fmaf(x2, wv.y, acc[2][1]);
            acc[2][2] = fmaf(x2, wv.z, acc[2][2]);
            acc[2][3] = fmaf(x2, wv.w, acc[2][3]);
            acc[3][0] = fmaf(x3, wv.x, acc[3][0]);
            acc[3][1] = fmaf(x3, wv.y, acc[3][1]);
            acc[3][2] = fmaf(x3, wv.z, acc[3][2]);
            acc[3][3] = fmaf(x3, wv.w, acc[3][3]);
        }
        #pragma unroll
        for (int r = 0; r < 4; r++) {
            int gr = row0 + row4 + r;
            if (gr < nrows) {
                float4 o;
                o.x = fmaxf(acc[r][0], 0.0f);
                o.y = fmaxf(acc[r][1], 0.0f);
                o.z = fmaxf(acc[r][2], 0.0f);
                o.w = fmaxf(acc[r][3], 0.0f);
                *(float4*)&out[(size_t)gr * FF + col4] = o;
            }
        }
    }
}

// ---------------------------------------------------------------------------
// Final layer: out = log_softmax(in @ w4 + b4), K=128, C=40.
// ---------------------------------------------------------------------------
__global__ void k_final(const float* __restrict__ in, const float* __restrict__ w,
                        const float* __restrict__ bias, float* __restrict__ out,
                        int nrows) {
    __shared__ float ws[128 * 40];
    __shared__ float bs[40];
    __shared__ float xrow[8][128];
    int tid = threadIdx.x;
    for (int i = tid; i < 128 * 40; i += 256) ws[i] = w[i];
    if (tid < 40) bs[tid] = bias[tid];
    __syncthreads();
    int wid = tid >> 5, lane = tid & 31;
    for (int row = blockIdx.x * 8 + wid; row < nrows; row += gridDim.x * 8) {
        float4 xv = *(const float4*)&in[(size_t)row * FF + lane * 4];
        *(float4*)&xrow[wid][lane * 4] = xv;
        __syncwarp();
        float a0 = bs[lane];
        float a1 = (lane < 8) ? bs[32 + lane] : 0.0f;
        #pragma unroll 8
        for (int k = 0; k < 128; k++) {
            float xk = xrow[wid][k];
            a0 = fmaf(xk, ws[k * 40 + lane], a0);
            if (lane < 8) a1 = fmaf(xk, ws[k * 40 + 32 + lane], a1);
        }
        float m = a0;
        if (lane < 8) m = fmaxf(m, a1);
        #pragma unroll
        for (int d = 16; d; d >>= 1) m = fmaxf(m, __shfl_xor_sync(0xffffffffu, m, d));
        float s = expf(a0 - m) + ((lane < 8) ? expf(a1 - m) : 0.0f);
        #pragma unroll
        for (int d = 16; d; d >>= 1) s += __shfl_xor_sync(0xffffffffu, s, d);
        float lse = m + logf(s);
        out[(size_t)row * CC + lane] = a0 - lse;
        if (lane < 8) out[(size_t)row * CC + 32 + lane] = a1 - lse;
        __syncwarp();
    }
}

// ---------------------------------------------------------------------------
// Launcher
// ---------------------------------------------------------------------------
extern "C" void kernel_launch(void* const* d_in, const int* in_sizes, int n_in,
                              void* d_out, int out_size) {
    const float* x    = (const float*)d_in[0];
    const void*  ei   = d_in[1];
    const float* eps1 = (const float*)d_in[2];
    const float* w1   = (const float*)d_in[3];
    const float* b1   = (const float*)d_in[4];
    const float* w2   = (const float*)d_in[5];
    const float* b2   = (const float*)d_in[6];
    const float* eps2 = (const float*)d_in[7];
    const float* w3   = (const float*)d_in[8];
    const float* b3   = (const float*)d_in[9];
    const float* w4   = (const float*)d_in[10];
    const float* b4   = (const float*)d_in[11];
    float*       out  = (float*)d_out;

    int N = in_sizes[0] / FF;
    int E = in_sizes[1] / 2;
    if (N > NN) N = NN;
    if (E > EE) E = EE;

    const int smem_gemm = (16384 + 4096) * (int)sizeof(float);  // 80KB
    cudaFuncSetAttribute(k_gemm_relu, cudaFuncAttributeMaxDynamicSharedMemorySize,
                         smem_gemm);

    void *pA = nullptr, *pB = nullptr, *pC = nullptr;
    cudaGetSymbolAddress(&pA, g_bufA);
    cudaGetSymbolAddress(&pB, g_bufB);
    cudaGetSymbolAddress(&pC, g_bufC);
    float* bufA = (float*)pA;
    float* bufB = (float*)pB;
    float* bufC = (float*)pC;

    const int gemm_grid = 296;  // 2 blocks/SM * 148 SMs
    int scan_blocks = (N + 1 + 1023) / 1024;

    // Dtype sniff + CSR build (once per launch, reused by both aggregations)
    k_detect<<<1, 32>>>((const long long*)ei, E, N);
    k_zero_off<<<(N + 1 + 255) / 256, 256>>>(N);
    k_hist<<<(E + 255) / 256, 256>>>(ei, E, N);
    k_scan1<<<scan_blocks, 1024>>>(N);
    k_scan2<<<1, 128>>>(scan_blocks);
    k_scan3<<<scan_blocks, 1024>>>(N);
    k_scatter<<<(E + 255) / 256, 256>>>(ei, E, N);

    // Layer 1: agg -> Lin+ReLU -> Lin+ReLU
    {
        long long tw = (long long)N * 32;
        k_agg<<<(int)((tw + 255) / 256), 256>>>(x, bufA, eps1, N);
    }
    k_gemm_relu<<<gemm_grid, 256, smem_gemm>>>(bufA, w1, b1, bufB, N);
    k_gemm_relu<<<gemm_grid, 256, smem_gemm>>>(bufB, w2, b2, bufC, N);

    // Layer 2: agg -> Lin+ReLU -> Lin -> log_softmax
    {
        long long tw = (long long)N * 32;
        k_agg<<<(int)((tw + 255) / 256), 256>>>(bufC, bufA, eps2, N);
    }
    k_gemm_relu<<<gemm_grid, 256, smem_gemm>>>(bufA, w3, b3, bufB, N);
    k_final<<<(N + 7) / 8, 256>>>(bufB, w4, b4, out, N);
}

// round 6
// speedup vs baseline: 1.7525x; 1.5099x over previous
#include <cuda_runtime.h>
#include <cuda_bf16.h>
#include <math.h>
#include <stdint.h>

// Problem constants (fixed shapes per reference)
#define NN 100000
#define FF 128
#define CC 40
#define EE 1600000

// Scratch (device globals — no allocation allowed in kernel_launch)
__device__ float g_bufA[(size_t)NN * FF];
__device__ float g_bufB[(size_t)NN * FF];
__device__ float g_bufC[(size_t)NN * FF];
__device__ int   g_off[NN + 1];
__device__ int   g_cursor[NN];
__device__ int   g_ssrc[EE];
__device__ int   g_idx_is64;
__device__ int   g_bsum[128];

// ===========================================================================
// Dtype sniffer (parallel): edge_index may arrive as int64 or int32.
// ===========================================================================
__global__ void k_detect(const long long* __restrict__ ei, int e, int n) {
    int lane = threadIdx.x;
    long long step = e / 32; if (step < 1) step = 1;
    long long i = lane * step;
    int bad = 0;
    if (i < e) {
        long long v = ei[i];
        bad = (v < 0 || v >= n) ? 1 : 0;
    }
    unsigned m = __ballot_sync(0xffffffffu, bad);
    if (lane == 0) g_idx_is64 = (m == 0u) ? 1 : 0;
}

__device__ __forceinline__ int load_idx(const void* ei, long long elem, int is64) {
    return is64 ? (int)((const long long*)ei)[elem] : ((const int*)ei)[elem];
}

// ===========================================================================
// CSR construction: zero -> histogram -> hierarchical scan -> scatter
// ===========================================================================
__global__ void k_zero_off(int n) {
    int i = blockIdx.x * blockDim.x + threadIdx.x;
    if (i <= n) g_off[i] = 0;
}

__global__ void k_hist(const void* __restrict__ ei, int e, int n) {
    int i = blockIdx.x * blockDim.x + threadIdx.x;
    if (i >= e) return;
    int is64 = g_idx_is64;
    int d = load_idx(ei, (long long)e + i, is64);
    if ((unsigned)d < (unsigned)n) atomicAdd(&g_off[d + 1], 1);
}

__global__ void k_scan1(int n) {
    __shared__ int wsum[32];
    int tid = threadIdx.x, lane = tid & 31, wid = tid >> 5;
    int gid = blockIdx.x * 1024 + tid;
    int v = (gid <= n) ? g_off[gid] : 0;
    #pragma unroll
    for (int d = 1; d < 32; d <<= 1) {
        int t = __shfl_up_sync(0xffffffffu, v, d);
        if (lane >= d) v += t;
    }
    if (lane == 31) wsum[wid] = v;
    __syncthreads();
    if (wid == 0) {
        int w = wsum[lane];
        #pragma unroll
        for (int d = 1; d < 32; d <<= 1) {
            int t = __shfl_up_sync(0xffffffffu, w, d);
            if (lane >= d) w += t;
        }
        wsum[lane] = w;
    }
    __syncthreads();
    if (wid > 0) v += wsum[wid - 1];
    if (gid <= n) g_off[gid] = v;
    if (tid == 1023) g_bsum[blockIdx.x] = v;
}

__global__ void k_scan2(int nblocks) {
    __shared__ int sh[128];
    int tid = threadIdx.x;
    int v = (tid < nblocks) ? g_bsum[tid] : 0;
    sh[tid] = v;
    __syncthreads();
    for (int d = 1; d < 128; d <<= 1) {
        int t = (tid >= d) ? sh[tid - d] : 0;
        __syncthreads();
        sh[tid] += t;
        __syncthreads();
    }
    int excl = (tid == 0) ? 0 : sh[tid - 1];
    if (tid < nblocks) g_bsum[tid] = excl;
}

__global__ void k_scan3(int n) {
    int gid = blockIdx.x * 1024 + threadIdx.x;
    if (gid > n) return;
    int v = g_off[gid] + g_bsum[blockIdx.x];
    g_off[gid] = v;
    if (gid < n) g_cursor[gid] = v;
}

__global__ void k_scatter(const void* __restrict__ ei, int e, int n) {
    int i = blockIdx.x * blockDim.x + threadIdx.x;
    if (i >= e) return;
    int is64 = g_idx_is64;
    int s = load_idx(ei, (long long)i, is64);
    int d = load_idx(ei, (long long)e + i, is64);
    if ((unsigned)d < (unsigned)n && (unsigned)s < (unsigned)n) {
        int pos = atomicAdd(&g_cursor[d], 1);
        if (pos < EE) g_ssrc[pos] = s;
    }
}

// ===========================================================================
// GIN aggregation: out[i] = (1+eps)*h[i] + sum_{j->i} h[j]
// ===========================================================================
__global__ void k_agg(const float* __restrict__ hin, float* __restrict__ hout,
                      const float* __restrict__ epsp, int n) {
    int g = blockIdx.x * blockDim.x + threadIdx.x;
    int node = g >> 5;
    if (node >= n) return;
    int lane = g & 31;
    float sc = 1.0f + *epsp;
    const float4* base = (const float4*)hin;
    float4 acc = __ldg(&base[(size_t)node * 32 + lane]);
    acc.x *= sc; acc.y *= sc; acc.z *= sc; acc.w *= sc;
    int beg = g_off[node], end = g_off[node + 1];
    #pragma unroll 4
    for (int e = beg; e < end; e++) {
        int s = g_ssrc[e];
        float4 v = __ldg(&base[(size_t)s * 32 + lane]);
        acc.x += v.x; acc.y += v.y; acc.z += v.z; acc.w += v.w;
    }
    *(float4*)&hout[(size_t)node * FF + lane * 4] = acc;
}

// ===========================================================================
// Tensor-core GEMM+ReLU via mma.sync (HMMA), bf16 hi/lo split, f32 accum.
// out = relu(in @ w + b), K=128, OUT=128.
// Block: 256 thr (8 warps). Output tile 64 rows x 128 cols (grid-stride).
// Warp tile 32x32: wr = wid&1 (row half), wc = wid>>1 (col quarter).
// smem: Whi/Wlo [128][136] bf16, Ahi/Alo [64][136] bf16 (136-pad = no conflicts)
// ===========================================================================
#define STR 136
#define GM_SMEM ((128 * STR * 2 * 2) + (64 * STR * 2 * 2))   // 104448 bytes

__device__ __forceinline__ void split2(float x, float y, uint32_t& hi, uint32_t& lo) {
    __nv_bfloat162 h = __floats2bfloat162_rn(x, y);
    float rx = x - __bfloat162float(h.x);
    float ry = y - __bfloat162float(h.y);
    __nv_bfloat162 l = __floats2bfloat162_rn(rx, ry);
    hi = *(uint32_t*)&h;
    lo = *(uint32_t*)&l;
}

__device__ __forceinline__ void mma_bf16(float& c0, float& c1, float& c2, float& c3,
                                         uint32_t a0, uint32_t a1, uint32_t a2, uint32_t a3,
                                         uint32_t b0, uint32_t b1) {
    asm volatile(
        "mma.sync.aligned.m16n8k16.row.col.f32.bf16.bf16.f32 "
        "{%0,%1,%2,%3}, {%4,%5,%6,%7}, {%8,%9}, {%0,%1,%2,%3};"
        : "+f"(c0), "+f"(c1), "+f"(c2), "+f"(c3)
        : "r"(a0), "r"(a1), "r"(a2), "r"(a3), "r"(b0), "r"(b1));
}

__global__ void __launch_bounds__(256, 2)
k_gemm_mma(const float* __restrict__ in, const float* __restrict__ w,
           const float* __restrict__ bias, float* __restrict__ out,
           int nrows, int do_relu) {
    extern __shared__ __align__(16) uint16_t smu[];
    uint16_t* Whi = smu;                         // [128][STR]
    uint16_t* Wlo = Whi + 128 * STR;
    uint16_t* Ahi = Wlo + 128 * STR;             // [64][STR]
    uint16_t* Alo = Ahi + 64 * STR;
    __shared__ float sbias[128];

    int tid = threadIdx.x, lane = tid & 31, wid = tid >> 5;
    if (tid < 128) sbias[tid] = bias[tid];

    // --- Convert W (transposed) into Whi/Wlo: Ws[n][k] = w[k][n] ---
    // 8192 tasks: n = i&127 (coalesced reads), k pair = (i>>7)*2
    for (int i = tid; i < 8192; i += 256) {
        int n = i & 127;
        int k0 = (i >> 7) * 2;
        float va = w[k0 * 128 + n];
        float vb = w[(k0 + 1) * 128 + n];
        uint32_t hi, lo;
        split2(va, vb, hi, lo);
        *(uint32_t*)&Whi[n * STR + k0] = hi;
        *(uint32_t*)&Wlo[n * STR + k0] = lo;
    }
    __syncthreads();

    int g = lane >> 2;          // group 0..7
    int tq = lane & 3;          // quad thread 0..3
    int wr = wid & 1;           // row half
    int wc = wid >> 1;          // col quarter
    int ntiles = (nrows + 63) / 64;

    for (int tile = blockIdx.x; tile < ntiles; tile += gridDim.x) {
        int row0 = tile * 64;
        // --- Load + convert x tile into Ahi/Alo ---
        #pragma unroll
        for (int it = 0; it < 4; it++) {
            int task = tid + 256 * it;       // 1024 tasks: 64 rows x 16 chunks
            int r = task >> 4;
            int c0 = (task & 15) * 8;
            int gr = row0 + r;
            float v[8];
            if (gr < nrows) {
                float4 p0 = *(const float4*)&in[(size_t)gr * 128 + c0];
                float4 p1 = *(const float4*)&in[(size_t)gr * 128 + c0 + 4];
                v[0] = p0.x; v[1] = p0.y; v[2] = p0.z; v[3] = p0.w;
                v[4] = p1.x; v[5] = p1.y; v[6] = p1.z; v[7] = p1.w;
            } else {
                #pragma unroll
                for (int j = 0; j < 8; j++) v[j] = 0.0f;
            }
            #pragma unroll
            for (int j = 0; j < 4; j++) {
                uint32_t hi, lo;
                split2(v[2 * j], v[2 * j + 1], hi, lo);
                *(uint32_t*)&Ahi[r * STR + c0 + 2 * j] = hi;
                *(uint32_t*)&Alo[r * STR + c0 + 2 * j] = lo;
            }
        }
        __syncthreads();

        // --- Mainloop: D += Ah*Bh + Ah*Bl + Al*Bh ---
        float acc[2][4][4];
        #pragma unroll
        for (int nt = 0; nt < 4; nt++) {
            float bx = sbias[wc * 32 + nt * 8 + 2 * tq];
            float by = sbias[wc * 32 + nt * 8 + 2 * tq + 1];
            #pragma unroll
            for (int mt = 0; mt < 2; mt++) {
                acc[mt][nt][0] = bx; acc[mt][nt][1] = by;
                acc[mt][nt][2] = bx; acc[mt][nt][3] = by;
            }
        }
        int arow0 = wr * 32 + g;      // A fragment row (lane-level)
        int brow  = wc * 32 + g;      // B fragment n-row base
        #pragma unroll
        for (int k0 = 0; k0 < 8; k0++) {
            int kk = k0 * 16 + 2 * tq;
            uint32_t ah[2][4], al[2][4], bh[4][2], bl[4][2];
            #pragma unroll
            for (int mt = 0; mt < 2; mt++) {
                int rbase = (arow0 + mt * 16) * STR + kk;
                ah[mt][0] = *(const uint32_t*)&Ahi[rbase];
                ah[mt][1] = *(const uint32_t*)&Ahi[rbase + 8 * STR];
                ah[mt][2] = *(const uint32_t*)&Ahi[rbase + 8];
                ah[mt][3] = *(const uint32_t*)&Ahi[rbase + 8 * STR + 8];
                al[mt][0] = *(const uint32_t*)&Alo[rbase];
                al[mt][1] = *(const uint32_t*)&Alo[rbase + 8 * STR];
                al[mt][2] = *(const uint32_t*)&Alo[rbase + 8];
                al[mt][3] = *(const uint32_t*)&Alo[rbase + 8 * STR + 8];
            }
            #pragma unroll
            for (int nt = 0; nt < 4; nt++) {
                int nbase = (brow + nt * 8) * STR + kk;
                bh[nt][0] = *(const uint32_t*)&Whi[nbase];
                bh[nt][1] = *(const uint32_t*)&Whi[nbase + 8];
                bl[nt][0] = *(const uint32_t*)&Wlo[nbase];
                bl[nt][1] = *(const uint32_t*)&Wlo[nbase + 8];
            }
            #pragma unroll
            for (int mt = 0; mt < 2; mt++)
                #pragma unroll
                for (int nt = 0; nt < 4; nt++) {
                    mma_bf16(acc[mt][nt][0], acc[mt][nt][1], acc[mt][nt][2], acc[mt][nt][3],
                             ah[mt][0], ah[mt][1], ah[mt][2], ah[mt][3],
                             bh[nt][0], bh[nt][1]);
                    mma_bf16(acc[mt][nt][0], acc[mt][nt][1], acc[mt][nt][2], acc[mt][nt][3],
                             ah[mt][0], ah[mt][1], ah[mt][2], ah[mt][3],
                             bl[nt][0], bl[nt][1]);
                    mma_bf16(acc[mt][nt][0], acc[mt][nt][1], acc[mt][nt][2], acc[mt][nt][3],
                             al[mt][0], al[mt][1], al[mt][2], al[mt][3],
                             bh[nt][0], bh[nt][1]);
                }
        }

        // --- Epilogue: relu + store ---
        #pragma unroll
        for (int mt = 0; mt < 2; mt++) {
            int gr0 = row0 + wr * 32 + mt * 16 + g;
            #pragma unroll
            for (int nt = 0; nt < 4; nt++) {
                int col = wc * 32 + nt * 8 + 2 * tq;
                if (do_relu) {
                    acc[mt][nt][0] = fmaxf(acc[mt][nt][0], 0.0f);
                    acc[mt][nt][1] = fmaxf(acc[mt][nt][1], 0.0f);
                    acc[mt][nt][2] = fmaxf(acc[mt][nt][2], 0.0f);
                    acc[mt][nt][3] = fmaxf(acc[mt][nt][3], 0.0f);
                }
                if (gr0 < nrows)
                    *(float2*)&out[(size_t)gr0 * 128 + col] =
                        make_float2(acc[mt][nt][0], acc[mt][nt][1]);
                if (gr0 + 8 < nrows)
                    *(float2*)&out[(size_t)(gr0 + 8) * 128 + col] =
                        make_float2(acc[mt][nt][2], acc[mt][nt][3]);
            }
        }
        __syncthreads();   // protect smem A before next iteration's convert
    }
}

// ===========================================================================
// Final layer: out = log_softmax(in @ w4 + b4), K=128, C=40.
// ===========================================================================
__global__ void k_final(const float* __restrict__ in, const float* __restrict__ w,
                        const float* __restrict__ bias, float* __restrict__ out,
                        int nrows) {
    __shared__ float ws[128 * 40];
    __shared__ float bs[40];
    __shared__ float xrow[8][128];
    int tid = threadIdx.x;
    for (int i = tid; i < 128 * 40; i += 256) ws[i] = w[i];
    if (tid < 40) bs[tid] = bias[tid];
    __syncthreads();
    int wid = tid >> 5, lane = tid & 31;
    for (int row = blockIdx.x * 8 + wid; row < nrows; row += gridDim.x * 8) {
        float4 xv = *(const float4*)&in[(size_t)row * FF + lane * 4];
        *(float4*)&xrow[wid][lane * 4] = xv;
        __syncwarp();
        float a0 = bs[lane];
        float a1 = (lane < 8) ? bs[32 + lane] : 0.0f;
        #pragma unroll 8
        for (int k = 0; k < 128; k++) {
            float xk = xrow[wid][k];
            a0 = fmaf(xk, ws[k * 40 + lane], a0);
            if (lane < 8) a1 = fmaf(xk, ws[k * 40 + 32 + lane], a1);
        }
        float m = a0;
        if (lane < 8) m = fmaxf(m, a1);
        #pragma unroll
        for (int d = 16; d; d >>= 1) m = fmaxf(m, __shfl_xor_sync(0xffffffffu, m, d));
        float s = expf(a0 - m) + ((lane < 8) ? expf(a1 - m) : 0.0f);
        #pragma unroll
        for (int d = 16; d; d >>= 1) s += __shfl_xor_sync(0xffffffffu, s, d);
        float lse = m + logf(s);
        out[(size_t)row * CC + lane] = a0 - lse;
        if (lane < 8) out[(size_t)row * CC + 32 + lane] = a1 - lse;
        __syncwarp();
    }
}

// ===========================================================================
// Launcher
// ===========================================================================
extern "C" void kernel_launch(void* const* d_in, const int* in_sizes, int n_in,
                              void* d_out, int out_size) {
    const float* x    = (const float*)d_in[0];
    const void*  ei   = d_in[1];
    const float* eps1 = (const float*)d_in[2];
    const float* w1   = (const float*)d_in[3];
    const float* b1   = (const float*)d_in[4];
    const float* w2   = (const float*)d_in[5];
    const float* b2   = (const float*)d_in[6];
    const float* eps2 = (const float*)d_in[7];
    const float* w3   = (const float*)d_in[8];
    const float* b3   = (const float*)d_in[9];
    const float* w4   = (const float*)d_in[10];
    const float* b4   = (const float*)d_in[11];
    float*       out  = (float*)d_out;

    int N = in_sizes[0] / FF;
    int E = in_sizes[1] / 2;
    if (N > NN) N = NN;
    if (E > EE) E = EE;

    cudaFuncSetAttribute(k_gemm_mma, cudaFuncAttributeMaxDynamicSharedMemorySize, GM_SMEM);

    void *pA = nullptr, *pB = nullptr, *pC = nullptr;
    cudaGetSymbolAddress(&pA, g_bufA);
    cudaGetSymbolAddress(&pB, g_bufB);
    cudaGetSymbolAddress(&pC, g_bufC);
    float* bufA = (float*)pA;
    float* bufB = (float*)pB;
    float* bufC = (float*)pC;

    int scan_blocks = (N + 1 + 1023) / 1024;

    // Dtype sniff + CSR build
    k_detect<<<1, 32>>>((const long long*)ei, E, N);
    k_zero_off<<<(N + 1 + 255) / 256, 256>>>(N);
    k_hist<<<(E + 255) / 256, 256>>>(ei, E, N);
    k_scan1<<<scan_blocks, 1024>>>(N);
    k_scan2<<<1, 128>>>(scan_blocks);
    k_scan3<<<scan_blocks, 1024>>>(N);
    k_scatter<<<(E + 255) / 256, 256>>>(ei, E, N);

    // Layer 1: agg -> Lin+ReLU -> Lin+ReLU
    {
        long long tw = (long long)N * 32;
        k_agg<<<(int)((tw + 255) / 256), 256>>>(x, bufA, eps1, N);
    }
    k_gemm_mma<<<296, 256, GM_SMEM>>>(bufA, w1, b1, bufB, N, 1);
    k_gemm_mma<<<296, 256, GM_SMEM>>>(bufB, w2, b2, bufC, N, 1);

    // Layer 2: agg -> Lin+ReLU -> Lin -> log_softmax
    {
        long long tw = (long long)N * 32;
        k_agg<<<(int)((tw + 255) / 256), 256>>>(bufC, bufA, eps2, N);
    }
    k_gemm_mma<<<296, 256, GM_SMEM>>>(bufA, w3, b3, bufB, N, 1);
    k_final<<<(N + 7) / 8, 256>>>(bufB, w4, b4, out, N);
}

// round 8
// speedup vs baseline: 2.2465x; 1.2819x over previous
#include <cuda_runtime.h>
#include <cuda_bf16.h>
#include <math.h>
#include <stdint.h>

// Problem constants (fixed shapes per reference)
#define NN 100000
#define FF 128
#define CC 40
#define EE 1600000

// Scratch (device globals — no allocation allowed in kernel_launch)
__device__ float g_bufA[(size_t)NN * FF];
__device__ float g_bufB[(size_t)NN * FF];
__device__ float g_bufC[(size_t)NN * FF];
__device__ int   g_off[NN + 1];
__device__ int   g_cursor[NN];
__device__ int   g_ssrc[EE];
__device__ int   g_idx_is64;
__device__ int   g_bsum[128];

// ===========================================================================
// Dtype sniffer (parallel): edge_index may arrive as int64 or int32.
// ===========================================================================
__global__ void k_detect(const long long* __restrict__ ei, int e, int n) {
    int lane = threadIdx.x;
    long long step = e / 32; if (step < 1) step = 1;
    long long i = lane * step;
    int bad = 0;
    if (i < e) {
        long long v = ei[i];
        bad = (v < 0 || v >= n) ? 1 : 0;
    }
    unsigned m = __ballot_sync(0xffffffffu, bad);
    if (lane == 0) g_idx_is64 = (m == 0u) ? 1 : 0;
}

__device__ __forceinline__ int load_idx(const void* ei, long long elem, int is64) {
    return is64 ? (int)((const long long*)ei)[elem] : ((const int*)ei)[elem];
}

// ===========================================================================
// CSR construction: zero -> histogram -> hierarchical scan -> scatter
// ===========================================================================
__global__ void k_zero_off(int n) {
    int i = blockIdx.x * blockDim.x + threadIdx.x;
    if (i <= n) g_off[i] = 0;
}

__global__ void k_hist(const void* __restrict__ ei, int e, int n) {
    int i = blockIdx.x * blockDim.x + threadIdx.x;
    if (i >= e) return;
    int is64 = g_idx_is64;
    int d = load_idx(ei, (long long)e + i, is64);
    if ((unsigned)d < (unsigned)n) atomicAdd(&g_off[d + 1], 1);
}

__global__ void k_scan1(int n) {
    __shared__ int wsum[32];
    int tid = threadIdx.x, lane = tid & 31, wid = tid >> 5;
    int gid = blockIdx.x * 1024 + tid;
    int v = (gid <= n) ? g_off[gid] : 0;
    #pragma unroll
    for (int d = 1; d < 32; d <<= 1) {
        int t = __shfl_up_sync(0xffffffffu, v, d);
        if (lane >= d) v += t;
    }
    if (lane == 31) wsum[wid] = v;
    __syncthreads();
    if (wid == 0) {
        int w = wsum[lane];
        #pragma unroll
        for (int d = 1; d < 32; d <<= 1) {
            int t = __shfl_up_sync(0xffffffffu, w, d);
            if (lane >= d) w += t;
        }
        wsum[lane] = w;
    }
    __syncthreads();
    if (wid > 0) v += wsum[wid - 1];
    if (gid <= n) g_off[gid] = v;
    if (tid == 1023) g_bsum[blockIdx.x] = v;
}

__global__ void k_scan2(int nblocks) {
    __shared__ int sh[128];
    int tid = threadIdx.x;
    int v = (tid < nblocks) ? g_bsum[tid] : 0;
    sh[tid] = v;
    __syncthreads();
    for (int d = 1; d < 128; d <<= 1) {
        int t = (tid >= d) ? sh[tid - d] : 0;
        __syncthreads();
        sh[tid] += t;
        __syncthreads();
    }
    int excl = (tid == 0) ? 0 : sh[tid - 1];
    if (tid < nblocks) g_bsum[tid] = excl;
}

__global__ void k_scan3(int n) {
    int gid = blockIdx.x * 1024 + threadIdx.x;
    if (gid > n) return;
    int v = g_off[gid] + g_bsum[blockIdx.x];
    g_off[gid] = v;
    if (gid < n) g_cursor[gid] = v;
}

__global__ void k_scatter(const void* __restrict__ ei, int e, int n) {
    int i = blockIdx.x * blockDim.x + threadIdx.x;
    if (i >= e) return;
    int is64 = g_idx_is64;
    int s = load_idx(ei, (long long)i, is64);
    int d = load_idx(ei, (long long)e + i, is64);
    if ((unsigned)d < (unsigned)n && (unsigned)s < (unsigned)n) {
        int pos = atomicAdd(&g_cursor[d], 1);
        if (pos < EE) g_ssrc[pos] = s;
    }
}

// ===========================================================================
// GIN aggregation: out[i] = (1+eps)*h[i] + sum_{j->i} h[j]
// One warp per node; dual accumulators to deepen load pipelining.
// ===========================================================================
__global__ void k_agg(const float* __restrict__ hin, float* __restrict__ hout,
                      const float* __restrict__ epsp, int n) {
    int g = blockIdx.x * blockDim.x + threadIdx.x;
    int node = g >> 5;
    if (node >= n) return;
    int lane = g & 31;
    float sc = 1.0f + *epsp;
    const float4* base = (const float4*)hin;
    float4 acc = __ldg(&base[(size_t)node * 32 + lane]);
    acc.x *= sc; acc.y *= sc; acc.z *= sc; acc.w *= sc;
    float4 acc2 = make_float4(0.f, 0.f, 0.f, 0.f);
    int beg = g_off[node], end = g_off[node + 1];
    int e = beg;
    #pragma unroll 2
    for (; e + 1 < end; e += 2) {
        int s0 = g_ssrc[e];
        int s1 = g_ssrc[e + 1];
        float4 v0 = __ldg(&base[(size_t)s0 * 32 + lane]);
        float4 v1 = __ldg(&base[(size_t)s1 * 32 + lane]);
        acc.x += v0.x; acc.y += v0.y; acc.z += v0.z; acc.w += v0.w;
        acc2.x += v1.x; acc2.y += v1.y; acc2.z += v1.z; acc2.w += v1.w;
    }
    if (e < end) {
        int s = g_ssrc[e];
        float4 v = __ldg(&base[(size_t)s * 32 + lane]);
        acc.x += v.x; acc.y += v.y; acc.z += v.z; acc.w += v.w;
    }
    acc.x += acc2.x; acc.y += acc2.y; acc.z += acc2.z; acc.w += acc2.w;
    *(float4*)&hout[(size_t)node * FF + lane * 4] = acc;
}

// ===========================================================================
// Tensor-core GEMM+ReLU via mma.sync (HMMA), bf16 hi/lo split, f32 accum.
// (verified round-6 version, unchanged)
// ===========================================================================
#define STR 136
#define GM_SMEM ((128 * STR * 2 * 2) + (64 * STR * 2 * 2))   // 104448 bytes

__device__ __forceinline__ void split2(float x, float y, uint32_t& hi, uint32_t& lo) {
    __nv_bfloat162 h = __floats2bfloat162_rn(x, y);
    float rx = x - __bfloat162float(h.x);
    float ry = y - __bfloat162float(h.y);
    __nv_bfloat162 l = __floats2bfloat162_rn(rx, ry);
    hi = *(uint32_t*)&h;
    lo = *(uint32_t*)&l;
}

__device__ __forceinline__ void mma_bf16(float& c0, float& c1, float& c2, float& c3,
                                         uint32_t a0, uint32_t a1, uint32_t a2, uint32_t a3,
                                         uint32_t b0, uint32_t b1) {
    asm volatile(
        "mma.sync.aligned.m16n8k16.row.col.f32.bf16.bf16.f32 "
        "{%0,%1,%2,%3}, {%4,%5,%6,%7}, {%8,%9}, {%0,%1,%2,%3};"
        : "+f"(c0), "+f"(c1), "+f"(c2), "+f"(c3)
        : "r"(a0), "r"(a1), "r"(a2), "r"(a3), "r"(b0), "r"(b1));
}

__global__ void __launch_bounds__(256, 2)
k_gemm_mma(const float* __restrict__ in, const float* __restrict__ w,
           const float* __restrict__ bias, float* __restrict__ out,
           int nrows, int do_relu) {
    extern __shared__ __align__(16) uint16_t smu[];
    uint16_t* Whi = smu;                         // [128][STR]
    uint16_t* Wlo = Whi + 128 * STR;
    uint16_t* Ahi = Wlo + 128 * STR;             // [64][STR]
    uint16_t* Alo = Ahi + 64 * STR;
    __shared__ float sbias[128];

    int tid = threadIdx.x, lane = tid & 31, wid = tid >> 5;
    if (tid < 128) sbias[tid] = bias[tid];

    for (int i = tid; i < 8192; i += 256) {
        int n = i & 127;
        int k0 = (i >> 7) * 2;
        float va = w[k0 * 128 + n];
        float vb = w[(k0 + 1) * 128 + n];
        uint32_t hi, lo;
        split2(va, vb, hi, lo);
        *(uint32_t*)&Whi[n * STR + k0] = hi;
        *(uint32_t*)&Wlo[n * STR + k0] = lo;
    }
    __syncthreads();

    int g = lane >> 2;
    int tq = lane & 3;
    int wr = wid & 1;
    int wc = wid >> 1;
    int ntiles = (nrows + 63) / 64;

    for (int tile = blockIdx.x; tile < ntiles; tile += gridDim.x) {
        int row0 = tile * 64;
        #pragma unroll
        for (int it = 0; it < 4; it++) {
            int task = tid + 256 * it;
            int r = task >> 4;
            int c0 = (task & 15) * 8;
            int gr = row0 + r;
            float v[8];
            if (gr < nrows) {
                float4 p0 = *(const float4*)&in[(size_t)gr * 128 + c0];
                float4 p1 = *(const float4*)&in[(size_t)gr * 128 + c0 + 4];
                v[0] = p0.x; v[1] = p0.y; v[2] = p0.z; v[3] = p0.w;
                v[4] = p1.x; v[5] = p1.y; v[6] = p1.z; v[7] = p1.w;
            } else {
                #pragma unroll
                for (int j = 0; j < 8; j++) v[j] = 0.0f;
            }
            #pragma unroll
            for (int j = 0; j < 4; j++) {
                uint32_t hi, lo;
                split2(v[2 * j], v[2 * j + 1], hi, lo);
                *(uint32_t*)&Ahi[r * STR + c0 + 2 * j] = hi;
                *(uint32_t*)&Alo[r * STR + c0 + 2 * j] = lo;
            }
        }
        __syncthreads();

        float acc[2][4][4];
        #pragma unroll
        for (int nt = 0; nt < 4; nt++) {
            float bx = sbias[wc * 32 + nt * 8 + 2 * tq];
            float by = sbias[wc * 32 + nt * 8 + 2 * tq + 1];
            #pragma unroll
            for (int mt = 0; mt < 2; mt++) {
                acc[mt][nt][0] = bx; acc[mt][nt][1] = by;
                acc[mt][nt][2] = bx; acc[mt][nt][3] = by;
            }
        }
        int arow0 = wr * 32 + g;
        int brow  = wc * 32 + g;
        #pragma unroll
        for (int k0 = 0; k0 < 8; k0++) {
            int kk = k0 * 16 + 2 * tq;
            uint32_t ah[2][4], al[2][4], bh[4][2], bl[4][2];
            #pragma unroll
            for (int mt = 0; mt < 2; mt++) {
                int rbase = (arow0 + mt * 16) * STR + kk;
                ah[mt][0] = *(const uint32_t*)&Ahi[rbase];
                ah[mt][1] = *(const uint32_t*)&Ahi[rbase + 8 * STR];
                ah[mt][2] = *(const uint32_t*)&Ahi[rbase + 8];
                ah[mt][3] = *(const uint32_t*)&Ahi[rbase + 8 * STR + 8];
                al[mt][0] = *(const uint32_t*)&Alo[rbase];
                al[mt][1] = *(const uint32_t*)&Alo[rbase + 8 * STR];
                al[mt][2] = *(const uint32_t*)&Alo[rbase + 8];
                al[mt][3] = *(const uint32_t*)&Alo[rbase + 8 * STR + 8];
            }
            #pragma unroll
            for (int nt = 0; nt < 4; nt++) {
                int nbase = (brow + nt * 8) * STR + kk;
                bh[nt][0] = *(const uint32_t*)&Whi[nbase];
                bh[nt][1] = *(const uint32_t*)&Whi[nbase + 8];
                bl[nt][0] = *(const uint32_t*)&Wlo[nbase];
                bl[nt][1] = *(const uint32_t*)&Wlo[nbase + 8];
            }
            #pragma unroll
            for (int mt = 0; mt < 2; mt++)
                #pragma unroll
                for (int nt = 0; nt < 4; nt++) {
                    mma_bf16(acc[mt][nt][0], acc[mt][nt][1], acc[mt][nt][2], acc[mt][nt][3],
                             ah[mt][0], ah[mt][1], ah[mt][2], ah[mt][3],
                             bh[nt][0], bh[nt][1]);
                    mma_bf16(acc[mt][nt][0], acc[mt][nt][1], acc[mt][nt][2], acc[mt][nt][3],
                             ah[mt][0], ah[mt][1], ah[mt][2], ah[mt][3],
                             bl[nt][0], bl[nt][1]);
                    mma_bf16(acc[mt][nt][0], acc[mt][nt][1], acc[mt][nt][2], acc[mt][nt][3],
                             al[mt][0], al[mt][1], al[mt][2], al[mt][3],
                             bh[nt][0], bh[nt][1]);
                }
        }

        #pragma unroll
        for (int mt = 0; mt < 2; mt++) {
            int gr0 = row0 + wr * 32 + mt * 16 + g;
            #pragma unroll
            for (int nt = 0; nt < 4; nt++) {
                int col = wc * 32 + nt * 8 + 2 * tq;
                if (do_relu) {
                    acc[mt][nt][0] = fmaxf(acc[mt][nt][0], 0.0f);
                    acc[mt][nt][1] = fmaxf(acc[mt][nt][1], 0.0f);
                    acc[mt][nt][2] = fmaxf(acc[mt][nt][2], 0.0f);
                    acc[mt][nt][3] = fmaxf(acc[mt][nt][3], 0.0f);
                }
                if (gr0 < nrows)
                    *(float2*)&out[(size_t)gr0 * 128 + col] =
                        make_float2(acc[mt][nt][0], acc[mt][nt][1]);
                if (gr0 + 8 < nrows)
                    *(float2*)&out[(size_t)(gr0 + 8) * 128 + col] =
                        make_float2(acc[mt][nt][2], acc[mt][nt][3]);
            }
        }
        __syncthreads();
    }
}

// ===========================================================================
// Final layer (tensor-core, fused): out = log_softmax(in @ w4 + b4).
// W4 [128][40] zero-padded to 64 cols. Tile 64 rows. Warp tile 32x16.
// acc -> smem (only cols < 40 stored; stride 41) -> per-row warp log_softmax.
// ===========================================================================
#define FM_SMEM (4 * 64 * STR * 2 + 64 * 41 * 4 + 256)

__global__ void __launch_bounds__(256, 2)
k_final_mma(const float* __restrict__ in, const float* __restrict__ w,
            const float* __restrict__ bias, float* __restrict__ out, int nrows) {
    extern __shared__ __align__(16) uint16_t smu[];
    uint16_t* W4hi = smu;                        // [64][STR]
    uint16_t* W4lo = W4hi + 64 * STR;
    uint16_t* Ahi  = W4lo + 64 * STR;            // [64][STR]
    uint16_t* Alo  = Ahi + 64 * STR;
    float* sacc = (float*)(Alo + 64 * STR);      // [64][41]
    float* sb   = sacc + 64 * 41;                // [64]

    int tid = threadIdx.x, lane = tid & 31, wid = tid >> 5;
    if (tid < 64) sb[tid] = (tid < CC) ? bias[tid] : 0.0f;

    // Convert W4 transposed+padded: W4s[n][k] = (n<40) ? w4[k][n] : 0
    for (int i = tid; i < 64 * 64; i += 256) {
        int n = i & 63;
        int k0 = (i >> 6) * 2;
        float va = (n < CC) ? w[k0 * CC + n] : 0.0f;
        float vb = (n < CC) ? w[(k0 + 1) * CC + n] : 0.0f;
        uint32_t hi, lo;
        split2(va, vb, hi, lo);
        *(uint32_t*)&W4hi[n * STR + k0] = hi;
        *(uint32_t*)&W4lo[n * STR + k0] = lo;
    }
    __syncthreads();

    int g = lane >> 2;
    int tq = lane & 3;
    int wr = wid & 1;          // row half (32 rows)
    int wc = wid >> 1;         // col group of 16 (4 groups -> 64 cols)
    int ntiles = (nrows + 63) / 64;

    for (int tile = blockIdx.x; tile < ntiles; tile += gridDim.x) {
        int row0 = tile * 64;
        // Load + convert x tile
        #pragma unroll
        for (int it = 0; it < 4; it++) {
            int task = tid + 256 * it;
            int r = task >> 4;
            int c0 = (task & 15) * 8;
            int gr = row0 + r;
            float v[8];
            if (gr < nrows) {
                float4 p0 = *(const float4*)&in[(size_t)gr * 128 + c0];
                float4 p1 = *(const float4*)&in[(size_t)gr * 128 + c0 + 4];
                v[0] = p0.x; v[1] = p0.y; v[2] = p0.z; v[3] = p0.w;
                v[4] = p1.x; v[5] = p1.y; v[6] = p1.z; v[7] = p1.w;
            } else {
                #pragma unroll
                for (int j = 0; j < 8; j++) v[j] = 0.0f;
            }
            #pragma unroll
            for (int j = 0; j < 4; j++) {
                uint32_t hi, lo;
                split2(v[2 * j], v[2 * j + 1], hi, lo);
                *(uint32_t*)&Ahi[r * STR + c0 + 2 * j] = hi;
                *(uint32_t*)&Alo[r * STR + c0 + 2 * j] = lo;
            }
        }
        __syncthreads();

        // MMA: warp tile 32 rows x 16 cols
        float acc[2][2][4];
        #pragma unroll
        for (int nt = 0; nt < 2; nt++) {
            float bx = sb[wc * 16 + nt * 8 + 2 * tq];
            float by = sb[wc * 16 + nt * 8 + 2 * tq + 1];
            #pragma unroll
            for (int mt = 0; mt < 2; mt++) {
                acc[mt][nt][0] = bx; acc[mt][nt][1] = by;
                acc[mt][nt][2] = bx; acc[mt][nt][3] = by;
            }
        }
        int arow0 = wr * 32 + g;
        int brow  = wc * 16 + g;
        #pragma unroll
        for (int k0 = 0; k0 < 8; k0++) {
            int kk = k0 * 16 + 2 * tq;
            uint32_t ah[2][4], al[2][4], bh[2][2], bl[2][2];
            #pragma unroll
            for (int mt = 0; mt < 2; mt++) {
                int rbase = (arow0 + mt * 16) * STR + kk;
                ah[mt][0] = *(const uint32_t*)&Ahi[rbase];
                ah[mt][1] = *(const uint32_t*)&Ahi[rbase + 8 * STR];
                ah[mt][2] = *(const uint32_t*)&Ahi[rbase + 8];
                ah[mt][3] = *(const uint32_t*)&Ahi[rbase + 8 * STR + 8];
                al[mt][0] = *(const uint32_t*)&Alo[rbase];
                al[mt][1] = *(const uint32_t*)&Alo[rbase + 8 * STR];
                al[mt][2] = *(const uint32_t*)&Alo[rbase + 8];
                al[mt][3] = *(const uint32_t*)&Alo[rbase + 8 * STR + 8];
            }
            #pragma unroll
            for (int nt = 0; nt < 2; nt++) {
                int nbase = (brow + nt * 8) * STR + kk;
                bh[nt][0] = *(const uint32_t*)&W4hi[nbase];
                bh[nt][1] = *(const uint32_t*)&W4hi[nbase + 8];
                bl[nt][0] = *(const uint32_t*)&W4lo[nbase];
                bl[nt][1] = *(const uint32_t*)&W4lo[nbase + 8];
            }
            #pragma unroll
            for (int mt = 0; mt < 2; mt++)
                #pragma unroll
                for (int nt = 0; nt < 2; nt++) {
                    mma_bf16(acc[mt][nt][0], acc[mt][nt][1], acc[mt][nt][2], acc[mt][nt][3],
                             ah[mt][0], ah[mt][1], ah[mt][2], ah[mt][3],
                             bh[nt][0], bh[nt][1]);
                    mma_bf16(acc[mt][nt][0], acc[mt][nt][1], acc[mt][nt][2], acc[mt][nt][3],
                             ah[mt][0], ah[mt][1], ah[mt][2], ah[mt][3],
                             bl[nt][0], bl[nt][1]);
                    mma_bf16(acc[mt][nt][0], acc[mt][nt][1], acc[mt][nt][2], acc[mt][nt][3],
                             al[mt][0], al[mt][1], al[mt][2], al[mt][3],
                             bh[nt][0], bh[nt][1]);
                }
        }

        // acc -> smem. ONLY cols < CC=40 (stride is 41; padded cols 40..63
        // must NOT be stored — they would overflow into the next row).
        #pragma unroll
        for (int mt = 0; mt < 2; mt++) {
            int r0 = wr * 32 + mt * 16 + g;
            #pragma unroll
            for (int nt = 0; nt < 2; nt++) {
                int col = wc * 16 + nt * 8 + 2 * tq;
                if (col < CC) {   // pairs are aligned: col,col+1 both <40 or both >=40
                    sacc[r0 * 41 + col]       = acc[mt][nt][0];
                    sacc[r0 * 41 + col + 1]   = acc[mt][nt][1];
                    sacc[(r0 + 8) * 41 + col]     = acc[mt][nt][2];
                    sacc[(r0 + 8) * 41 + col + 1] = acc[mt][nt][3];
                }
            }
        }
        __syncthreads();

        // log_softmax: warp wid handles rows wid*8 .. wid*8+7
        #pragma unroll
        for (int rr = 0; rr < 8; rr++) {
            int r = wid * 8 + rr;
            int gr = row0 + r;
            float a0 = sacc[r * 41 + lane];
            float a1 = (lane < 8) ? sacc[r * 41 + 32 + lane] : -1e30f;
            float m = fmaxf(a0, a1);
            #pragma unroll
            for (int d = 16; d; d >>= 1) m = fmaxf(m, __shfl_xor_sync(0xffffffffu, m, d));
            float s = expf(a0 - m) + ((lane < 8) ? expf(a1 - m) : 0.0f);
            #pragma unroll
            for (int d = 16; d; d >>= 1) s += __shfl_xor_sync(0xffffffffu, s, d);
            float lse = m + logf(s);
            if (gr < nrows) {
                out[(size_t)gr * CC + lane] = a0 - lse;
                if (lane < 8) out[(size_t)gr * CC + 32 + lane] = a1 - lse;
            }
        }
        __syncthreads();
    }
}

// ===========================================================================
// Launcher
// ===========================================================================
extern "C" void kernel_launch(void* const* d_in, const int* in_sizes, int n_in,
                              void* d_out, int out_size) {
    const float* x    = (const float*)d_in[0];
    const void*  ei   = d_in[1];
    const float* eps1 = (const float*)d_in[2];
    const float* w1   = (const float*)d_in[3];
    const float* b1   = (const float*)d_in[4];
    const float* w2   = (const float*)d_in[5];
    const float* b2   = (const float*)d_in[6];
    const float* eps2 = (const float*)d_in[7];
    const float* w3   = (const float*)d_in[8];
    const float* b3   = (const float*)d_in[9];
    const float* w4   = (const float*)d_in[10];
    const float* b4   = (const float*)d_in[11];
    float*       out  = (float*)d_out;

    int N = in_sizes[0] / FF;
    int E = in_sizes[1] / 2;
    if (N > NN) N = NN;
    if (E > EE) E = EE;

    cudaFuncSetAttribute(k_gemm_mma, cudaFuncAttributeMaxDynamicSharedMemorySize, GM_SMEM);
    cudaFuncSetAttribute(k_final_mma, cudaFuncAttributeMaxDynamicSharedMemorySize, FM_SMEM);

    void *pA = nullptr, *pB = nullptr, *pC = nullptr;
    cudaGetSymbolAddress(&pA, g_bufA);
    cudaGetSymbolAddress(&pB, g_bufB);
    cudaGetSymbolAddress(&pC, g_bufC);
    float* bufA = (float*)pA;
    float* bufB = (float*)pB;
    float* bufC = (float*)pC;

    int scan_blocks = (N + 1 + 1023) / 1024;

    // Dtype sniff + CSR build
    k_detect<<<1, 32>>>((const long long*)ei, E, N);
    k_zero_off<<<(N + 1 + 255) / 256, 256>>>(N);
    k_hist<<<(E + 255) / 256, 256>>>(ei, E, N);
    k_scan1<<<scan_blocks, 1024>>>(N);
    k_scan2<<<1, 128>>>(scan_blocks);
    k_scan3<<<scan_blocks, 1024>>>(N);
    k_scatter<<<(E + 255) / 256, 256>>>(ei, E, N);

    // Layer 1: agg -> Lin+ReLU -> Lin+ReLU
    {
        long long tw = (long long)N * 32;
        k_agg<<<(int)((tw + 255) / 256), 256>>>(x, bufA, eps1, N);
    }
    k_gemm_mma<<<296, 256, GM_SMEM>>>(bufA, w1, b1, bufB, N, 1);
    k_gemm_mma<<<296, 256, GM_SMEM>>>(bufB, w2, b2, bufC, N, 1);

    // Layer 2: agg -> Lin+ReLU -> Lin -> log_softmax
    {
        long long tw = (long long)N * 32;
        k_agg<<<(int)((tw + 255) / 256), 256>>>(bufC, bufA, eps2, N);
    }
    k_gemm_mma<<<296, 256, GM_SMEM>>>(bufA, w3, b3, bufB, N, 1);
    k_final_mma<<<296, 256, FM_SMEM>>>(bufB, w4, b4, out, N);
}

// round 9
// speedup vs baseline: 2.2869x; 1.0180x over previous
#include <cuda_runtime.h>
#include <cuda_bf16.h>
#include <math.h>
#include <stdint.h>

// Problem constants (fixed shapes per reference)
#define NN 100000
#define FF 128
#define CC 40
#define EE 1600000

// Scratch (device globals — no allocation allowed in kernel_launch)
__device__ float g_bufA[(size_t)NN * FF];
__device__ float g_bufB[(size_t)NN * FF];
__device__ float g_bufC[(size_t)NN * FF];
__device__ int   g_off[NN + 1];
__device__ int   g_cursor[NN];
__device__ int   g_ssrc[EE];
__device__ int   g_idx_is64;
__device__ int   g_bsum[128];

// ===========================================================================
// Dtype sniffer (parallel): edge_index may arrive as int64 or int32.
// ===========================================================================
__global__ void k_detect(const long long* __restrict__ ei, int e, int n) {
    int lane = threadIdx.x;
    long long step = e / 32; if (step < 1) step = 1;
    long long i = lane * step;
    int bad = 0;
    if (i < e) {
        long long v = ei[i];
        bad = (v < 0 || v >= n) ? 1 : 0;
    }
    unsigned m = __ballot_sync(0xffffffffu, bad);
    if (lane == 0) g_idx_is64 = (m == 0u) ? 1 : 0;
}

__device__ __forceinline__ int load_idx(const void* ei, long long elem, int is64) {
    return is64 ? (int)((const long long*)ei)[elem] : ((const int*)ei)[elem];
}

// ===========================================================================
// CSR construction: zero -> histogram -> hierarchical scan -> scatter
// ===========================================================================
__global__ void k_zero_off(int n) {
    int i = blockIdx.x * blockDim.x + threadIdx.x;
    if (i <= n) g_off[i] = 0;
}

__global__ void k_hist(const void* __restrict__ ei, int e, int n) {
    int i = blockIdx.x * blockDim.x + threadIdx.x;
    if (i >= e) return;
    int is64 = g_idx_is64;
    int d = load_idx(ei, (long long)e + i, is64);
    if ((unsigned)d < (unsigned)n) atomicAdd(&g_off[d + 1], 1);
}

__global__ void k_scan1(int n) {
    __shared__ int wsum[32];
    int tid = threadIdx.x, lane = tid & 31, wid = tid >> 5;
    int gid = blockIdx.x * 1024 + tid;
    int v = (gid <= n) ? g_off[gid] : 0;
    #pragma unroll
    for (int d = 1; d < 32; d <<= 1) {
        int t = __shfl_up_sync(0xffffffffu, v, d);
        if (lane >= d) v += t;
    }
    if (lane == 31) wsum[wid] = v;
    __syncthreads();
    if (wid == 0) {
        int w = wsum[lane];
        #pragma unroll
        for (int d = 1; d < 32; d <<= 1) {
            int t = __shfl_up_sync(0xffffffffu, w, d);
            if (lane >= d) w += t;
        }
        wsum[lane] = w;
    }
    __syncthreads();
    if (wid > 0) v += wsum[wid - 1];
    if (gid <= n) g_off[gid] = v;
    if (tid == 1023) g_bsum[blockIdx.x] = v;
}

__global__ void k_scan2(int nblocks) {
    __shared__ int sh[128];
    int tid = threadIdx.x;
    int v = (tid < nblocks) ? g_bsum[tid] : 0;
    sh[tid] = v;
    __syncthreads();
    for (int d = 1; d < 128; d <<= 1) {
        int t = (tid >= d) ? sh[tid - d] : 0;
        __syncthreads();
        sh[tid] += t;
        __syncthreads();
    }
    int excl = (tid == 0) ? 0 : sh[tid - 1];
    if (tid < nblocks) g_bsum[tid] = excl;
}

__global__ void k_scan3(int n) {
    int gid = blockIdx.x * 1024 + threadIdx.x;
    if (gid > n) return;
    int v = g_off[gid] + g_bsum[blockIdx.x];
    g_off[gid] = v;
    if (gid < n) g_cursor[gid] = v;
}

__global__ void k_scatter(const void* __restrict__ ei, int e, int n) {
    int i = blockIdx.x * blockDim.x + threadIdx.x;
    if (i >= e) return;
    int is64 = g_idx_is64;
    int s = load_idx(ei, (long long)i, is64);
    int d = load_idx(ei, (long long)e + i, is64);
    if ((unsigned)d < (unsigned)n && (unsigned)s < (unsigned)n) {
        int pos = atomicAdd(&g_cursor[d], 1);
        if (pos < EE) g_ssrc[pos] = s;
    }
}

// ===========================================================================
// GIN aggregation: out[i] = (1+eps)*h[i] + sum_{j->i} h[j]
// One warp per node; 4-wide edge unroll for deeper load pipelining.
// ===========================================================================
__global__ void k_agg(const float* __restrict__ hin, float* __restrict__ hout,
                      const float* __restrict__ epsp, int n) {
    int g = blockIdx.x * blockDim.x + threadIdx.x;
    int node = g >> 5;
    if (node >= n) return;
    int lane = g & 31;
    float sc = 1.0f + *epsp;
    const float4* base = (const float4*)hin;
    float4 acc = __ldg(&base[(size_t)node * 32 + lane]);
    acc.x *= sc; acc.y *= sc; acc.z *= sc; acc.w *= sc;
    float4 acc2 = make_float4(0.f, 0.f, 0.f, 0.f);
    int beg = g_off[node], end = g_off[node + 1];
    int e = beg;
    for (; e + 3 < end; e += 4) {
        int s0 = g_ssrc[e];
        int s1 = g_ssrc[e + 1];
        int s2 = g_ssrc[e + 2];
        int s3 = g_ssrc[e + 3];
        float4 v0 = __ldg(&base[(size_t)s0 * 32 + lane]);
        float4 v1 = __ldg(&base[(size_t)s1 * 32 + lane]);
        float4 v2 = __ldg(&base[(size_t)s2 * 32 + lane]);
        float4 v3 = __ldg(&base[(size_t)s3 * 32 + lane]);
        acc.x += v0.x; acc.y += v0.y; acc.z += v0.z; acc.w += v0.w;
        acc2.x += v1.x; acc2.y += v1.y; acc2.z += v1.z; acc2.w += v1.w;
        acc.x += v2.x; acc.y += v2.y; acc.z += v2.z; acc.w += v2.w;
        acc2.x += v3.x; acc2.y += v3.y; acc2.z += v3.z; acc2.w += v3.w;
    }
    for (; e < end; e++) {
        int s = g_ssrc[e];
        float4 v = __ldg(&base[(size_t)s * 32 + lane]);
        acc.x += v.x; acc.y += v.y; acc.z += v.z; acc.w += v.w;
    }
    acc.x += acc2.x; acc.y += acc2.y; acc.z += acc2.z; acc.w += acc2.w;
    *(float4*)&hout[(size_t)node * FF + lane * 4] = acc;
}

// ===========================================================================
// Tensor-core GEMM+ReLU via mma.sync (HMMA), bf16 hi/lo split, f32 accum.
// Mainloop fragment loads via ldmatrix.m8n8.x4 (8 LDSM/k-step vs 32 LDS).
// ===========================================================================
#define STR 136
#define GM_SMEM ((128 * STR * 2 * 2) + (64 * STR * 2 * 2))   // 104448 bytes

__device__ __forceinline__ uint32_t smem_u32(const void* p) {
    uint32_t a;
    asm("{ .reg .u64 t; cvta.to.shared.u64 t, %1; cvt.u32.u64 %0, t; }" : "=r"(a) : "l"(p));
    return a;
}

__device__ __forceinline__ void split2(float x, float y, uint32_t& hi, uint32_t& lo) {
    __nv_bfloat162 h = __floats2bfloat162_rn(x, y);
    float rx = x - __bfloat162float(h.x);
    float ry = y - __bfloat162float(h.y);
    __nv_bfloat162 l = __floats2bfloat162_rn(rx, ry);
    hi = *(uint32_t*)&h;
    lo = *(uint32_t*)&l;
}

__device__ __forceinline__ void mma_bf16(float& c0, float& c1, float& c2, float& c3,
                                         uint32_t a0, uint32_t a1, uint32_t a2, uint32_t a3,
                                         uint32_t b0, uint32_t b1) {
    asm volatile(
        "mma.sync.aligned.m16n8k16.row.col.f32.bf16.bf16.f32 "
        "{%0,%1,%2,%3}, {%4,%5,%6,%7}, {%8,%9}, {%0,%1,%2,%3};"
        : "+f"(c0), "+f"(c1), "+f"(c2), "+f"(c3)
        : "r"(a0), "r"(a1), "r"(a2), "r"(a3), "r"(b0), "r"(b1));
}

__device__ __forceinline__ void ldsm4(uint32_t& r0, uint32_t& r1, uint32_t& r2,
                                      uint32_t& r3, uint32_t addr) {
    asm volatile("ldmatrix.sync.aligned.m8n8.x4.shared.b16 {%0,%1,%2,%3}, [%4];"
                 : "=r"(r0), "=r"(r1), "=r"(r2), "=r"(r3) : "r"(addr));
}

__global__ void __launch_bounds__(256, 2)
k_gemm_mma(const float* __restrict__ in, const float* __restrict__ w,
           const float* __restrict__ bias, float* __restrict__ out,
           int nrows, int do_relu) {
    extern __shared__ __align__(16) uint16_t smu[];
    uint16_t* Whi = smu;                         // [128][STR]
    uint16_t* Wlo = Whi + 128 * STR;
    uint16_t* Ahi = Wlo + 128 * STR;             // [64][STR]
    uint16_t* Alo = Ahi + 64 * STR;
    __shared__ float sbias[128];

    int tid = threadIdx.x, lane = tid & 31, wid = tid >> 5;
    if (tid < 128) sbias[tid] = bias[tid];

    for (int i = tid; i < 8192; i += 256) {
        int n = i & 127;
        int k0 = (i >> 7) * 2;
        float va = w[k0 * 128 + n];
        float vb = w[(k0 + 1) * 128 + n];
        uint32_t hi, lo;
        split2(va, vb, hi, lo);
        *(uint32_t*)&Whi[n * STR + k0] = hi;
        *(uint32_t*)&Wlo[n * STR + k0] = lo;
    }
    __syncthreads();

    int g = lane >> 2;
    int tq = lane & 3;
    int wr = wid & 1;
    int wc = wid >> 1;
    int ntiles = (nrows + 63) / 64;

    // ldmatrix lane-level addressing: m8 = matrix index group, rw = row in matrix
    int m8 = lane >> 3, rw = lane & 7;
    uint32_t sAhi = smem_u32(Ahi), sAlo = smem_u32(Alo);
    uint32_t sWhi = smem_u32(Whi), sWlo = smem_u32(Wlo);
    // A matrices (per mt): {m0: rows+0,k0-7 | m1: rows+8,k0-7 | m2: rows+0,k8-15 | m3: rows+8,k8-15}
    uint32_t aoff0 = (uint32_t)(((wr * 32 + 0 * 16 + (m8 & 1) * 8 + rw) * STR + (m8 >> 1) * 8) * 2);
    uint32_t aoff1 = (uint32_t)(((wr * 32 + 1 * 16 + (m8 & 1) * 8 + rw) * STR + (m8 >> 1) * 8) * 2);
    // B matrices (per nt-pair p): {m0: n+0,k0-7 | m1: n+0,k8-15 | m2: n+8,k0-7 | m3: n+8,k8-15}
    uint32_t boff0 = (uint32_t)(((wc * 32 + 0 * 16 + (m8 >> 1) * 8 + rw) * STR + (m8 & 1) * 8) * 2);
    uint32_t boff1 = (uint32_t)(((wc * 32 + 1 * 16 + (m8 >> 1) * 8 + rw) * STR + (m8 & 1) * 8) * 2);

    for (int tile = blockIdx.x; tile < ntiles; tile += gridDim.x) {
        int row0 = tile * 64;
        #pragma unroll
        for (int it = 0; it < 4; it++) {
            int task = tid + 256 * it;
            int r = task >> 4;
            int c0 = (task & 15) * 8;
            int gr = row0 + r;
            float v[8];
            if (gr < nrows) {
                float4 p0 = *(const float4*)&in[(size_t)gr * 128 + c0];
                float4 p1 = *(const float4*)&in[(size_t)gr * 128 + c0 + 4];
                v[0] = p0.x; v[1] = p0.y; v[2] = p0.z; v[3] = p0.w;
                v[4] = p1.x; v[5] = p1.y; v[6] = p1.z; v[7] = p1.w;
            } else {
                #pragma unroll
                for (int j = 0; j < 8; j++) v[j] = 0.0f;
            }
            #pragma unroll
            for (int j = 0; j < 4; j++) {
                uint32_t hi, lo;
                split2(v[2 * j], v[2 * j + 1], hi, lo);
                *(uint32_t*)&Ahi[r * STR + c0 + 2 * j] = hi;
                *(uint32_t*)&Alo[r * STR + c0 + 2 * j] = lo;
            }
        }
        __syncthreads();

        float acc[2][4][4];
        #pragma unroll
        for (int nt = 0; nt < 4; nt++) {
            float bx = sbias[wc * 32 + nt * 8 + 2 * tq];
            float by = sbias[wc * 32 + nt * 8 + 2 * tq + 1];
            #pragma unroll
            for (int mt = 0; mt < 2; mt++) {
                acc[mt][nt][0] = bx; acc[mt][nt][1] = by;
                acc[mt][nt][2] = bx; acc[mt][nt][3] = by;
            }
        }
        #pragma unroll
        for (int k0 = 0; k0 < 8; k0++) {
            uint32_t kb = (uint32_t)(k0 * 32);   // 16 cols * 2B
            uint32_t ah[2][4], al[2][4], bh4[2][4], bl4[2][4];
            ldsm4(ah[0][0], ah[0][1], ah[0][2], ah[0][3], sAhi + aoff0 + kb);
            ldsm4(ah[1][0], ah[1][1], ah[1][2], ah[1][3], sAhi + aoff1 + kb);
            ldsm4(al[0][0], al[0][1], al[0][2], al[0][3], sAlo + aoff0 + kb);
            ldsm4(al[1][0], al[1][1], al[1][2], al[1][3], sAlo + aoff1 + kb);
            ldsm4(bh4[0][0], bh4[0][1], bh4[0][2], bh4[0][3], sWhi + boff0 + kb);
            ldsm4(bh4[1][0], bh4[1][1], bh4[1][2], bh4[1][3], sWhi + boff1 + kb);
            ldsm4(bl4[0][0], bl4[0][1], bl4[0][2], bl4[0][3], sWlo + boff0 + kb);
            ldsm4(bl4[1][0], bl4[1][1], bl4[1][2], bl4[1][3], sWlo + boff1 + kb);
            #pragma unroll
            for (int mt = 0; mt < 2; mt++)
                #pragma unroll
                for (int nt = 0; nt < 4; nt++) {
                    uint32_t b0h = bh4[nt >> 1][(nt & 1) * 2];
                    uint32_t b1h = bh4[nt >> 1][(nt & 1) * 2 + 1];
                    uint32_t b0l = bl4[nt >> 1][(nt & 1) * 2];
                    uint32_t b1l = bl4[nt >> 1][(nt & 1) * 2 + 1];
                    mma_bf16(acc[mt][nt][0], acc[mt][nt][1], acc[mt][nt][2], acc[mt][nt][3],
                             ah[mt][0], ah[mt][1], ah[mt][2], ah[mt][3], b0h, b1h);
                    mma_bf16(acc[mt][nt][0], acc[mt][nt][1], acc[mt][nt][2], acc[mt][nt][3],
                             ah[mt][0], ah[mt][1], ah[mt][2], ah[mt][3], b0l, b1l);
                    mma_bf16(acc[mt][nt][0], acc[mt][nt][1], acc[mt][nt][2], acc[mt][nt][3],
                             al[mt][0], al[mt][1], al[mt][2], al[mt][3], b0h, b1h);
                }
        }

        #pragma unroll
        for (int mt = 0; mt < 2; mt++) {
            int gr0 = row0 + wr * 32 + mt * 16 + g;
            #pragma unroll
            for (int nt = 0; nt < 4; nt++) {
                int col = wc * 32 + nt * 8 + 2 * tq;
                if (do_relu) {
                    acc[mt][nt][0] = fmaxf(acc[mt][nt][0], 0.0f);
                    acc[mt][nt][1] = fmaxf(acc[mt][nt][1], 0.0f);
                    acc[mt][nt][2] = fmaxf(acc[mt][nt][2], 0.0f);
                    acc[mt][nt][3] = fmaxf(acc[mt][nt][3], 0.0f);
                }
                if (gr0 < nrows)
                    *(float2*)&out[(size_t)gr0 * 128 + col] =
                        make_float2(acc[mt][nt][0], acc[mt][nt][1]);
                if (gr0 + 8 < nrows)
                    *(float2*)&out[(size_t)(gr0 + 8) * 128 + col] =
                        make_float2(acc[mt][nt][2], acc[mt][nt][3]);
            }
        }
        __syncthreads();
    }
}

// ===========================================================================
// Final layer (tensor-core, fused): out = log_softmax(in @ w4 + b4).
// (verified round-8 version, unchanged)
// ===========================================================================
#define FM_SMEM (4 * 64 * STR * 2 + 64 * 41 * 4 + 256)

__global__ void __launch_bounds__(256, 2)
k_final_mma(const float* __restrict__ in, const float* __restrict__ w,
            const float* __restrict__ bias, float* __restrict__ out, int nrows) {
    extern __shared__ __align__(16) uint16_t smu[];
    uint16_t* W4hi = smu;                        // [64][STR]
    uint16_t* W4lo = W4hi + 64 * STR;
    uint16_t* Ahi  = W4lo + 64 * STR;            // [64][STR]
    uint16_t* Alo  = Ahi + 64 * STR;
    float* sacc = (float*)(Alo + 64 * STR);      // [64][41]
    float* sb   = sacc + 64 * 41;                // [64]

    int tid = threadIdx.x, lane = tid & 31, wid = tid >> 5;
    if (tid < 64) sb[tid] = (tid < CC) ? bias[tid] : 0.0f;

    for (int i = tid; i < 64 * 64; i += 256) {
        int n = i & 63;
        int k0 = (i >> 6) * 2;
        float va = (n < CC) ? w[k0 * CC + n] : 0.0f;
        float vb = (n < CC) ? w[(k0 + 1) * CC + n] : 0.0f;
        uint32_t hi, lo;
        split2(va, vb, hi, lo);
        *(uint32_t*)&W4hi[n * STR + k0] = hi;
        *(uint32_t*)&W4lo[n * STR + k0] = lo;
    }
    __syncthreads();

    int g = lane >> 2;
    int tq = lane & 3;
    int wr = wid & 1;
    int wc = wid >> 1;
    int ntiles = (nrows + 63) / 64;

    for (int tile = blockIdx.x; tile < ntiles; tile += gridDim.x) {
        int row0 = tile * 64;
        #pragma unroll
        for (int it = 0; it < 4; it++) {
            int task = tid + 256 * it;
            int r = task >> 4;
            int c0 = (task & 15) * 8;
            int gr = row0 + r;
            float v[8];
            if (gr < nrows) {
                float4 p0 = *(const float4*)&in[(size_t)gr * 128 + c0];
                float4 p1 = *(const float4*)&in[(size_t)gr * 128 + c0 + 4];
                v[0] = p0.x; v[1] = p0.y; v[2] = p0.z; v[3] = p0.w;
                v[4] = p1.x; v[5] = p1.y; v[6] = p1.z; v[7] = p1.w;
            } else {
                #pragma unroll
                for (int j = 0; j < 8; j++) v[j] = 0.0f;
            }
            #pragma unroll
            for (int j = 0; j < 4; j++) {
                uint32_t hi, lo;
                split2(v[2 * j], v[2 * j + 1], hi, lo);
                *(uint32_t*)&Ahi[r * STR + c0 + 2 * j] = hi;
                *(uint32_t*)&Alo[r * STR + c0 + 2 * j] = lo;
            }
        }
        __syncthreads();

        float acc[2][2][4];
        #pragma unroll
        for (int nt = 0; nt < 2; nt++) {
            float bx = sb[wc * 16 + nt * 8 + 2 * tq];
            float by = sb[wc * 16 + nt * 8 + 2 * tq + 1];
            #pragma unroll
            for (int mt = 0; mt < 2; mt++) {
                acc[mt][nt][0] = bx; acc[mt][nt][1] = by;
                acc[mt][nt][2] = bx; acc[mt][nt][3] = by;
            }
        }
        int arow0 = wr * 32 + g;
        int brow  = wc * 16 + g;
        #pragma unroll
        for (int k0 = 0; k0 < 8; k0++) {
            int kk = k0 * 16 + 2 * tq;
            uint32_t ah[2][4], al[2][4], bh[2][2], bl[2][2];
            #pragma unroll
            for (int mt = 0; mt < 2; mt++) {
                int rbase = (arow0 + mt * 16) * STR + kk;
                ah[mt][0] = *(const uint32_t*)&Ahi[rbase];
                ah[mt][1] = *(const uint32_t*)&Ahi[rbase + 8 * STR];
                ah[mt][2] = *(const uint32_t*)&Ahi[rbase + 8];
                ah[mt][3] = *(const uint32_t*)&Ahi[rbase + 8 * STR + 8];
                al[mt][0] = *(const uint32_t*)&Alo[rbase];
                al[mt][1] = *(const uint32_t*)&Alo[rbase + 8 * STR];
                al[mt][2] = *(const uint32_t*)&Alo[rbase + 8];
                al[mt][3] = *(const uint32_t*)&Alo[rbase + 8 * STR + 8];
            }
            #pragma unroll
            for (int nt = 0; nt < 2; nt++) {
                int nbase = (brow + nt * 8) * STR + kk;
                bh[nt][0] = *(const uint32_t*)&W4hi[nbase];
                bh[nt][1] = *(const uint32_t*)&W4hi[nbase + 8];
                bl[nt][0] = *(const uint32_t*)&W4lo[nbase];
                bl[nt][1] = *(const uint32_t*)&W4lo[nbase + 8];
            }
            #pragma unroll
            for (int mt = 0; mt < 2; mt++)
                #pragma unroll
                for (int nt = 0; nt < 2; nt++) {
                    mma_bf16(acc[mt][nt][0], acc[mt][nt][1], acc[mt][nt][2], acc[mt][nt][3],
                             ah[mt][0], ah[mt][1], ah[mt][2], ah[mt][3],
                             bh[nt][0], bh[nt][1]);
                    mma_bf16(acc[mt][nt][0], acc[mt][nt][1], acc[mt][nt][2], acc[mt][nt][3],
                             ah[mt][0], ah[mt][1], ah[mt][2], ah[mt][3],
                             bl[nt][0], bl[nt][1]);
                    mma_bf16(acc[mt][nt][0], acc[mt][nt][1], acc[mt][nt][2], acc[mt][nt][3],
                             al[mt][0], al[mt][1], al[mt][2], al[mt][3],
                             bh[nt][0], bh[nt][1]);
                }
        }

        #pragma unroll
        for (int mt = 0; mt < 2; mt++) {
            int r0 = wr * 32 + mt * 16 + g;
            #pragma unroll
            for (int nt = 0; nt < 2; nt++) {
                int col = wc * 16 + nt * 8 + 2 * tq;
                if (col < CC) {
                    sacc[r0 * 41 + col]       = acc[mt][nt][0];
                    sacc[r0 * 41 + col + 1]   = acc[mt][nt][1];
                    sacc[(r0 + 8) * 41 + col]     = acc[mt][nt][2];
                    sacc[(r0 + 8) * 41 + col + 1] = acc[mt][nt][3];
                }
            }
        }
        __syncthreads();

        #pragma unroll
        for (int rr = 0; rr < 8; rr++) {
            int r = wid * 8 + rr;
            int gr = row0 + r;
            float a0 = sacc[r * 41 + lane];
            float a1 = (lane < 8) ? sacc[r * 41 + 32 + lane] : -1e30f;
            float m = fmaxf(a0, a1);
            #pragma unroll
            for (int d = 16; d; d >>= 1) m = fmaxf(m, __shfl_xor_sync(0xffffffffu, m, d));
            float s = expf(a0 - m) + ((lane < 8) ? expf(a1 - m) : 0.0f);
            #pragma unroll
            for (int d = 16; d; d >>= 1) s += __shfl_xor_sync(0xffffffffu, s, d);
            float lse = m + logf(s);
            if (gr < nrows) {
                out[(size_t)gr * CC + lane] = a0 - lse;
                if (lane < 8) out[(size_t)gr * CC + 32 + lane] = a1 - lse;
            }
        }
        __syncthreads();
    }
}

// ===========================================================================
// Launcher
// ===========================================================================
extern "C" void kernel_launch(void* const* d_in, const int* in_sizes, int n_in,
                              void* d_out, int out_size) {
    const float* x    = (const float*)d_in[0];
    const void*  ei   = d_in[1];
    const float* eps1 = (const float*)d_in[2];
    const float* w1   = (const float*)d_in[3];
    const float* b1   = (const float*)d_in[4];
    const float* w2   = (const float*)d_in[5];
    const float* b2   = (const float*)d_in[6];
    const float* eps2 = (const float*)d_in[7];
    const float* w3   = (const float*)d_in[8];
    const float* b3   = (const float*)d_in[9];
    const float* w4   = (const float*)d_in[10];
    const float* b4   = (const float*)d_in[11];
    float*       out  = (float*)d_out;

    int N = in_sizes[0] / FF;
    int E = in_sizes[1] / 2;
    if (N > NN) N = NN;
    if (E > EE) E = EE;

    cudaFuncSetAttribute(k_gemm_mma, cudaFuncAttributeMaxDynamicSharedMemorySize, GM_SMEM);
    cudaFuncSetAttribute(k_final_mma, cudaFuncAttributeMaxDynamicSharedMemorySize, FM_SMEM);

    void *pA = nullptr, *pB = nullptr, *pC = nullptr;
    cudaGetSymbolAddress(&pA, g_bufA);
    cudaGetSymbolAddress(&pB, g_bufB);
    cudaGetSymbolAddress(&pC, g_bufC);
    float* bufA = (float*)pA;
    float* bufB = (float*)pB;
    float* bufC = (float*)pC;

    int scan_blocks = (N + 1 + 1023) / 1024;

    // Dtype sniff + CSR build
    k_detect<<<1, 32>>>((const long long*)ei, E, N);
    k_zero_off<<<(N + 1 + 255) / 256, 256>>>(N);
    k_hist<<<(E + 255) / 256, 256>>>(ei, E, N);
    k_scan1<<<scan_blocks, 1024>>>(N);
    k_scan2<<<1, 128>>>(scan_blocks);
    k_scan3<<<scan_blocks, 1024>>>(N);
    k_scatter<<<(E + 255) / 256, 256>>>(ei, E, N);

    // Layer 1: agg -> Lin+ReLU -> Lin+ReLU
    {
        long long tw = (long long)N * 32;
        k_agg<<<(int)((tw + 255) / 256), 256>>>(x, bufA, eps1, N);
    }
    k_gemm_mma<<<296, 256, GM_SMEM>>>(bufA, w1, b1, bufB, N, 1);
    k_gemm_mma<<<296, 256, GM_SMEM>>>(bufB, w2, b2, bufC, N, 1);

    // Layer 2: agg -> Lin+ReLU -> Lin -> log_softmax
    {
        long long tw = (long long)N * 32;
        k_agg<<<(int)((tw + 255) / 256), 256>>>(bufC, bufA, eps2, N);
    }
    k_gemm_mma<<<296, 256, GM_SMEM>>>(bufA, w3, b3, bufB, N, 1);
    k_final_mma<<<296, 256, FM_SMEM>>>(bufB, w4, b4, out, N);
}